// round 7
// baseline (speedup 1.0000x reference)
#include <cuda_runtime.h>
#include <math.h>
#include <stdint.h>

#define B_ 8
#define S_ 1024
#define E_ 1024
#define H_ 16
#define D_ 64
#define F_ 4096
#define TOK (B_ * S_)  // 8192

// ---------------- scratch (static device globals; no allocation) ----------------
__device__ float g_nx [(size_t)TOK * E_];
__device__ float g_q  [(size_t)TOK * E_];
__device__ float g_k  [(size_t)TOK * E_];
__device__ float g_v  [(size_t)TOK * E_];
__device__ float g_o  [(size_t)TOK * E_];
__device__ float g_x1 [(size_t)TOK * E_];
__device__ float g_nx2[(size_t)TOK * E_];
__device__ float g_h1 [(size_t)TOK * F_];
__device__ float g_woT[(size_t)E_ * E_];   // Wo^T [N][K] tf32
__device__ float g_w1T[(size_t)F_ * E_];   // W1^T [F][E] tf32
__device__ float g_w2T[(size_t)E_ * F_];   // W2^T [E][F] tf32

// ---------------- helpers ----------------
__device__ __forceinline__ uint32_t f2tf32(float x) {
    uint32_t r;
    asm("cvt.rna.tf32.f32 %0, %1;" : "=r"(r) : "f"(x));
    return r;
}
__device__ __forceinline__ float f2tf32f(float x) {
    return __uint_as_float(f2tf32(x));
}
__device__ __forceinline__ void cp_async16(void* smem, const void* gmem) {
    uint32_t s = (uint32_t)__cvta_generic_to_shared(smem);
    asm volatile("cp.async.cg.shared.global [%0], [%1], 16;\n" :: "r"(s), "l"(gmem));
}
#define CP_COMMIT() asm volatile("cp.async.commit_group;\n" ::: "memory")
#define CP_WAIT0()  asm volatile("cp.async.wait_group 0;\n" ::: "memory")
#define CP_WAIT1()  asm volatile("cp.async.wait_group 1;\n" ::: "memory")

__device__ __forceinline__ void mma_tf32(float c[4], const uint32_t a[4], const uint32_t b[2]) {
    asm volatile(
        "mma.sync.aligned.m16n8k8.row.col.f32.tf32.tf32.f32 "
        "{%0,%1,%2,%3}, {%4,%5,%6,%7}, {%8,%9}, {%0,%1,%2,%3};\n"
        : "+f"(c[0]), "+f"(c[1]), "+f"(c[2]), "+f"(c[3])
        : "r"(a[0]), "r"(a[1]), "r"(a[2]), "r"(a[3]), "r"(b[0]), "r"(b[1]));
}
__device__ __forceinline__ void ldsm_x4(uint32_t r[4], uint32_t saddr) {
    asm volatile("ldmatrix.sync.aligned.m8n8.x4.shared.b16 {%0,%1,%2,%3}, [%4];"
                 : "=r"(r[0]), "=r"(r[1]), "=r"(r[2]), "=r"(r[3]) : "r"(saddr));
}

// ---------------- weight transpose + tf32 round: in [K][N] -> out [N][K] ----------------
__global__ __launch_bounds__(256) void transpose_tf32_kernel(const float* __restrict__ in,
                                                             float* __restrict__ out,
                                                             int K, int N)
{
    __shared__ float tile[32][33];
    int bx = blockIdx.x;  // N / 32
    int by = blockIdx.y;  // K / 32
    int x = bx * 32 + threadIdx.x;           // n
    int y0 = by * 32 + threadIdx.y;          // k
#pragma unroll
    for (int j = 0; j < 32; j += 8)
        tile[threadIdx.y + j][threadIdx.x] = in[(size_t)(y0 + j) * N + x];
    __syncthreads();
    int xo = by * 32 + threadIdx.x;          // k
    int yo = bx * 32 + threadIdx.y;          // n
#pragma unroll
    for (int j = 0; j < 32; j += 8)
        out[(size_t)(yo + j) * K + xo] = f2tf32f(tile[threadIdx.x][threadIdx.y + j]);
}

// ---------------- LayerNorm: one block per row of 1024 ----------------
template <int TF32OUT>
__global__ __launch_bounds__(256) void ln_kernel(const float* __restrict__ x,
                                                 const float* __restrict__ g,
                                                 const float* __restrict__ be,
                                                 float* __restrict__ out)
{
    int row = blockIdx.x;
    int tid = threadIdx.x;
    const float4* xr = reinterpret_cast<const float4*>(x + (size_t)row * E_);
    float4 a = xr[tid];
    float s  = a.x + a.y + a.z + a.w;
    float ss = a.x * a.x + a.y * a.y + a.z * a.z + a.w * a.w;
#pragma unroll
    for (int o = 16; o > 0; o >>= 1) {
        s  += __shfl_xor_sync(0xffffffffu, s,  o);
        ss += __shfl_xor_sync(0xffffffffu, ss, o);
    }
    __shared__ float sm[8], sm2[8];
    int w = tid >> 5, lane = tid & 31;
    if (lane == 0) { sm[w] = s; sm2[w] = ss; }
    __syncthreads();
    if (tid < 32) {
        s  = (tid < 8) ? sm[tid]  : 0.f;
        ss = (tid < 8) ? sm2[tid] : 0.f;
#pragma unroll
        for (int o = 4; o > 0; o >>= 1) {
            s  += __shfl_xor_sync(0xffffffffu, s,  o);
            ss += __shfl_xor_sync(0xffffffffu, ss, o);
        }
        if (tid == 0) { sm[0] = s; sm2[0] = ss; }
    }
    __syncthreads();
    float mean = sm[0] * (1.0f / E_);
    float var  = sm2[0] * (1.0f / E_) - mean * mean;
    float inv  = rsqrtf(var + 1e-5f);
    float4 gg = reinterpret_cast<const float4*>(g)[tid];
    float4 bb = reinterpret_cast<const float4*>(be)[tid];
    float4 o4;
    o4.x = (a.x - mean) * inv * gg.x + bb.x;
    o4.y = (a.y - mean) * inv * gg.y + bb.y;
    o4.z = (a.z - mean) * inv * gg.z + bb.z;
    o4.w = (a.w - mean) * inv * gg.w + bb.w;
    if (TF32OUT) {
        o4.x = f2tf32f(o4.x); o4.y = f2tf32f(o4.y);
        o4.z = f2tf32f(o4.z); o4.w = f2tf32f(o4.w);
    }
    reinterpret_cast<float4*>(out + (size_t)row * E_)[tid] = o4;
}

// ---------------- QKV projections: per (64-token tile, head, batch) ----------------
__global__ __launch_bounds__(256) void qkv_kernel(const float* __restrict__ nx,
                                                  const float* __restrict__ Wq,
                                                  const float* __restrict__ Wk,
                                                  const float* __restrict__ Wv,
                                                  float* __restrict__ q,
                                                  float* __restrict__ k,
                                                  float* __restrict__ v)
{
    int st = blockIdx.x, h = blockIdx.y, b = blockIdx.z;
    __shared__ float Xs[64][65];
    __shared__ float Ws[64][65];
    int tid = threadIdx.x;
    int tx = tid & 15, ty = tid >> 4;
#pragma unroll
    for (int it = 0; it < 4; it++) {
        int idx = tid + it * 256;
        int r = idx >> 4, c4 = (idx & 15) * 4;
        const float* src = nx + ((size_t)(b * S_ + st * 64 + r)) * E_ + h * 64 + c4;
        float4 a = *reinterpret_cast<const float4*>(src);
        Xs[r][c4] = a.x; Xs[r][c4 + 1] = a.y; Xs[r][c4 + 2] = a.z; Xs[r][c4 + 3] = a.w;
    }
    const float* Wm[3] = {Wq, Wk, Wv};
    float*       Om[3] = {q, k, v};
    size_t obase = ((size_t)(b * H_ + h) * S_ + st * 64) * D_;
#pragma unroll 1
    for (int m = 0; m < 3; m++) {
        __syncthreads();
#pragma unroll
        for (int it = 0; it < 4; it++) {
            int idx = tid + it * 256;
            int r = idx >> 4, c4 = (idx & 15) * 4;
            float4 a = *reinterpret_cast<const float4*>(Wm[m] + r * 64 + c4);
            Ws[r][c4] = a.x; Ws[r][c4 + 1] = a.y; Ws[r][c4 + 2] = a.z; Ws[r][c4 + 3] = a.w;
        }
        __syncthreads();
        float acc[4][4] = {};
#pragma unroll 4
        for (int d = 0; d < 64; d++) {
            float av[4], bv[4];
#pragma unroll
            for (int i = 0; i < 4; i++) av[i] = Xs[ty * 4 + i][d];
#pragma unroll
            for (int j = 0; j < 4; j++) bv[j] = Ws[d][tx * 4 + j];
#pragma unroll
            for (int i = 0; i < 4; i++)
#pragma unroll
                for (int j = 0; j < 4; j++)
                    acc[i][j] = fmaf(av[i], bv[j], acc[i][j]);
        }
        float* dst = Om[m] + obase;
#pragma unroll
        for (int i = 0; i < 4; i++) {
            float4 o4 = {acc[i][0], acc[i][1], acc[i][2], acc[i][3]};
            *reinterpret_cast<float4*>(dst + (ty * 4 + i) * 64 + tx * 4) = o4;
        }
    }
}

// ---------------- Causal flash attention, 64x64 tiles, mma.tf32 ----------------
#define QSTR 68
#define KSTR 68
#define VSTR 72
#define PSTR 68
#define ATTN_SMEM_BYTES ((64 * (QSTR + KSTR + VSTR + PSTR)) * 4)

__global__ __launch_bounds__(256) void attn_kernel(const float* __restrict__ q,
                                                   const float* __restrict__ k,
                                                   const float* __restrict__ v,
                                                   float* __restrict__ o)
{
    extern __shared__ float smem[];
    float* Qs = smem;
    float* Ks = Qs + 64 * QSTR;
    float* Vs = Ks + 64 * KSTR;
    float* Ps = Vs + 64 * VSTR;
    __shared__ float m_s[64], l_s[64], corr_s[64];

    int qt = blockIdx.x, h = blockIdx.y, b = blockIdx.z;
    int tid  = threadIdx.x;
    int lane = tid & 31, warp = tid >> 5;
    int wm = warp >> 1, wn = warp & 1;
    int m0 = wm * 16;
    int r4 = lane >> 2, c4 = lane & 3;
    int tx = tid & 15, ty = tid >> 4;
    const float scale = 0.03125f;
    size_t head_base = (size_t)(b * H_ + h) * S_ * D_;

#pragma unroll
    for (int it = 0; it < 4; it++) {
        int idx = tid + it * 256;
        int r = idx >> 4, c = (idx & 15) * 4;
        float4 a = *reinterpret_cast<const float4*>(q + head_base + (size_t)(qt * 64 + r) * 64 + c);
        float4 o4 = {f2tf32f(a.x * scale), f2tf32f(a.y * scale),
                     f2tf32f(a.z * scale), f2tf32f(a.w * scale)};
        *reinterpret_cast<float4*>(Qs + r * QSTR + c) = o4;
    }
    if (tid < 64) { m_s[tid] = -1e30f; l_s[tid] = 0.f; }

    float acc_o[4][4] = {};

    for (int kt = 0; kt <= qt; kt++) {
        __syncthreads();
#pragma unroll
        for (int it = 0; it < 4; it++) {
            int idx = tid + it * 256;
            int r = idx >> 4, c = (idx & 15) * 4;
            float4 a = *reinterpret_cast<const float4*>(k + head_base + (size_t)(kt * 64 + r) * 64 + c);
            float4 k4 = {f2tf32f(a.x), f2tf32f(a.y), f2tf32f(a.z), f2tf32f(a.w)};
            *reinterpret_cast<float4*>(Ks + r * KSTR + c) = k4;
            float4 bb = *reinterpret_cast<const float4*>(v + head_base + (size_t)(kt * 64 + r) * 64 + c);
            float4 v4 = {f2tf32f(bb.x), f2tf32f(bb.y), f2tf32f(bb.z), f2tf32f(bb.w)};
            *reinterpret_cast<float4*>(Vs + r * VSTR + c) = v4;
        }
        __syncthreads();

        float acc_s[4][4] = {};
#pragma unroll
        for (int ks = 0; ks < 8; ks++) {
            int kc = ks * 8;
            uint32_t a[4];
            a[0] = __float_as_uint(Qs[(m0 + r4) * QSTR + kc + c4]);
            a[1] = __float_as_uint(Qs[(m0 + r4 + 8) * QSTR + kc + c4]);
            a[2] = __float_as_uint(Qs[(m0 + r4) * QSTR + kc + c4 + 4]);
            a[3] = __float_as_uint(Qs[(m0 + r4 + 8) * QSTR + kc + c4 + 4]);
#pragma unroll
            for (int ni = 0; ni < 4; ni++) {
                int n0 = wn * 32 + ni * 8;
                uint32_t bf[2];
                bf[0] = __float_as_uint(Ks[(n0 + r4) * KSTR + kc + c4]);
                bf[1] = __float_as_uint(Ks[(n0 + r4) * KSTR + kc + c4 + 4]);
                mma_tf32(acc_s[ni], a, bf);
            }
        }
#pragma unroll
        for (int ni = 0; ni < 4; ni++) {
            int n0 = wn * 32 + ni * 8 + 2 * c4;
            *reinterpret_cast<float2*>(Ps + (m0 + r4) * PSTR + n0) =
                make_float2(acc_s[ni][0], acc_s[ni][1]);
            *reinterpret_cast<float2*>(Ps + (m0 + r4 + 8) * PSTR + n0) =
                make_float2(acc_s[ni][2], acc_s[ni][3]);
        }
        __syncthreads();

        bool diag = (kt == qt);
#pragma unroll
        for (int i = 0; i < 4; i++) {
            int r = ty * 4 + i;
            float4 s4 = *reinterpret_cast<float4*>(Ps + r * PSTR + tx * 4);
            float sv[4] = {s4.x, s4.y, s4.z, s4.w};
            if (diag) {
#pragma unroll
                for (int j = 0; j < 4; j++)
                    if (tx * 4 + j > r) sv[j] = -1e30f;
            }
            float mm = fmaxf(fmaxf(sv[0], sv[1]), fmaxf(sv[2], sv[3]));
#pragma unroll
            for (int off = 8; off > 0; off >>= 1)
                mm = fmaxf(mm, __shfl_xor_sync(0xffffffffu, mm, off, 16));
            float mo = m_s[r];
            float mn = fmaxf(mo, mm);
            float corr = expf(mo - mn);
            float e0 = expf(sv[0] - mn), e1 = expf(sv[1] - mn);
            float e2 = expf(sv[2] - mn), e3 = expf(sv[3] - mn);
            float rs = e0 + e1 + e2 + e3;
            float4 p4 = {f2tf32f(e0), f2tf32f(e1), f2tf32f(e2), f2tf32f(e3)};
            *reinterpret_cast<float4*>(Ps + r * PSTR + tx * 4) = p4;
#pragma unroll
            for (int off = 8; off > 0; off >>= 1)
                rs += __shfl_xor_sync(0xffffffffu, rs, off, 16);
            if (tx == 0) { m_s[r] = mn; l_s[r] = l_s[r] * corr + rs; corr_s[r] = corr; }
        }
        __syncthreads();

        float cr0 = corr_s[m0 + r4];
        float cr1 = corr_s[m0 + r4 + 8];
#pragma unroll
        for (int ni = 0; ni < 4; ni++) {
            acc_o[ni][0] *= cr0; acc_o[ni][1] *= cr0;
            acc_o[ni][2] *= cr1; acc_o[ni][3] *= cr1;
        }
#pragma unroll
        for (int ks = 0; ks < 8; ks++) {
            int kc = ks * 8;
            uint32_t a[4];
            a[0] = __float_as_uint(Ps[(m0 + r4) * PSTR + kc + c4]);
            a[1] = __float_as_uint(Ps[(m0 + r4 + 8) * PSTR + kc + c4]);
            a[2] = __float_as_uint(Ps[(m0 + r4) * PSTR + kc + c4 + 4]);
            a[3] = __float_as_uint(Ps[(m0 + r4 + 8) * PSTR + kc + c4 + 4]);
#pragma unroll
            for (int ni = 0; ni < 4; ni++) {
                int n0 = wn * 32 + ni * 8;
                uint32_t bf[2];
                bf[0] = __float_as_uint(Vs[(kc + c4) * VSTR + n0 + r4]);
                bf[1] = __float_as_uint(Vs[(kc + c4 + 4) * VSTR + n0 + r4]);
                mma_tf32(acc_o[ni], a, bf);
            }
        }
    }

    float inv0 = 1.0f / l_s[m0 + r4];
    float inv1 = 1.0f / l_s[m0 + r4 + 8];
    float* ob = o + ((size_t)(b * S_ + qt * 64)) * E_ + h * 64;
#pragma unroll
    for (int ni = 0; ni < 4; ni++) {
        int cc = wn * 32 + ni * 8 + 2 * c4;
        float2 o0 = {f2tf32f(acc_o[ni][0] * inv0), f2tf32f(acc_o[ni][1] * inv0)};
        float2 o1 = {f2tf32f(acc_o[ni][2] * inv1), f2tf32f(acc_o[ni][3] * inv1)};
        *reinterpret_cast<float2*>(ob + (size_t)(m0 + r4) * E_ + cc)     = o0;
        *reinterpret_cast<float2*>(ob + (size_t)(m0 + r4 + 8) * E_ + cc) = o1;
    }
}

// ---------------- TF32 tensor-core GEMM: 128x128x16 tiles, ldmatrix + 3-stage cp.async ----
// A [M][K] K-major (tf32-pre-rounded); Bt [N][K] K-major (tf32-pre-rounded).
// C = A @ Bt^T + bias (+relu)(+resid)(+tf32out)
#define BM 128
#define BN 128
#define BK 16
#define TSTR 20                       // BK + 4 pad; LDSM conflict-free
#define T_STAGE (BM * TSTR)           // 2560 floats per operand stage
#define GEMM_SMEM_BYTES (6 * T_STAGE * 4)   // 61440

template <int RELU, int RES, int TF32OUT>
__global__ __launch_bounds__(256) void tgemm_kernel(const float* __restrict__ A,
                                                    const float* __restrict__ Bt,
                                                    const float* __restrict__ bias,
                                                    const float* __restrict__ resid,
                                                    float* __restrict__ C,
                                                    int M, int N, int K)
{
    extern __shared__ float sh[];
    float* Asm = sh;                   // [3][BM][TSTR]
    float* Bsm = sh + 3 * T_STAGE;     // [3][BN][TSTR]

    const int tid  = threadIdx.x;
    const int lane = tid & 31;
    const int warp = tid >> 5;
    const int wm = warp >> 2;          // 0..1
    const int wn = warp & 3;           // 0..3
    const int m_w = wm * 64;
    const int n_w = wn * 32;
    const int r4 = lane >> 2;          // 0..7
    const int c4 = lane & 3;           // 0..3
    const int bx = blockIdx.x, by = blockIdx.y;

    const float* Ab = A  + (size_t)by * BM * K;
    const float* Bb = Bt + (size_t)bx * BN * K;

    // per-lane LDSM offsets (in floats, within a [row][TSTR] tile at given kc)
    const int mat = lane >> 3, mrow = lane & 7;
    const int aoff = (mrow + 8 * (mat & 1)) * TSTR + 4 * (mat >> 1);   // A: mats {m,k}{m+8,k}{m,k+4}{m+8,k+4}
    const int boff = (mrow + 8 * (mat >> 1)) * TSTR + 4 * (mat & 1);   // B: mats {n,k}{n,k+4}{n+8,k}{n+8,k+4}

    uint32_t AsmBase = (uint32_t)__cvta_generic_to_shared(Asm);
    uint32_t BsmBase = (uint32_t)__cvta_generic_to_shared(Bsm);

    auto load_tile = [&](int buf, int k0) {
        float* Ad = Asm + buf * T_STAGE;
        float* Bd = Bsm + buf * T_STAGE;
#pragma unroll
        for (int i = 0; i < 2; i++) {
            int idx = tid + i * 256;
            int row = idx >> 2, kq = (idx & 3) * 4;
            cp_async16(Ad + row * TSTR + kq, Ab + (size_t)row * K + k0 + kq);
        }
#pragma unroll
        for (int i = 0; i < 2; i++) {
            int idx = tid + i * 256;
            int row = idx >> 2, kq = (idx & 3) * 4;
            cp_async16(Bd + row * TSTR + kq, Bb + (size_t)row * K + k0 + kq);
        }
        CP_COMMIT();
    };

    float acc[4][4][4] = {};

    const int nT = K / BK;
    load_tile(0, 0);
    load_tile(1, BK);

#pragma unroll 1
    for (int t = 0; t < nT; t++) {
        if (t + 1 < nT) { CP_WAIT1(); } else { CP_WAIT0(); }
        __syncthreads();
        if (t + 2 < nT) load_tile((t + 2) % 3, (t + 2) * BK);

        uint32_t Ac = AsmBase + ((t % 3) * T_STAGE) * 4;
        uint32_t Bc = BsmBase + ((t % 3) * T_STAGE) * 4;
#pragma unroll
        for (int ks = 0; ks < 2; ks++) {
            const int kc = ks * 8;
            uint32_t a[4][4], b[4][2];
#pragma unroll
            for (int mi = 0; mi < 4; mi++) {
                uint32_t addr = Ac + ((m_w + mi * 16) * TSTR + kc + aoff) * 4;
                ldsm_x4(a[mi], addr);
            }
#pragma unroll
            for (int g = 0; g < 2; g++) {
                uint32_t r[4];
                uint32_t addr = Bc + ((n_w + g * 16) * TSTR + kc + boff) * 4;
                ldsm_x4(r, addr);
                b[g * 2][0]     = r[0]; b[g * 2][1]     = r[1];
                b[g * 2 + 1][0] = r[2]; b[g * 2 + 1][1] = r[3];
            }
#pragma unroll
            for (int mi = 0; mi < 4; mi++)
#pragma unroll
                for (int ni = 0; ni < 4; ni++)
                    mma_tf32(acc[mi][ni], a[mi], b[ni]);
        }
        // no trailing sync: leading sync next iter orders buffer reuse
    }

    // epilogue
    const int row_base = by * BM + m_w;
    const int col_base = bx * BN + n_w;
#pragma unroll
    for (int mi = 0; mi < 4; mi++) {
#pragma unroll
        for (int ni = 0; ni < 4; ni++) {
            int c0 = col_base + ni * 8 + 2 * c4;
            float2 bb = *reinterpret_cast<const float2*>(bias + c0);
#pragma unroll
            for (int half = 0; half < 2; half++) {
                int r0 = row_base + mi * 16 + r4 + half * 8;
                float v0 = acc[mi][ni][half * 2]     + bb.x;
                float v1 = acc[mi][ni][half * 2 + 1] + bb.y;
                if (RELU) { v0 = fmaxf(v0, 0.f); v1 = fmaxf(v1, 0.f); }
                if (RES) {
                    float2 rr = *reinterpret_cast<const float2*>(resid + (size_t)r0 * N + c0);
                    v0 += rr.x; v1 += rr.y;
                }
                if (TF32OUT) { v0 = f2tf32f(v0); v1 = f2tf32f(v1); }
                float2 o2 = {v0, v1};
                *reinterpret_cast<float2*>(C + (size_t)r0 * N + c0) = o2;
            }
        }
    }
}

// ---------------- launch ----------------
extern "C" void kernel_launch(void* const* d_in, const int* in_sizes, int n_in,
                              void* d_out, int out_size)
{
    (void)in_sizes; (void)n_in; (void)out_size;
    const float* x   = (const float*)d_in[0];
    const float* Wq  = (const float*)d_in[1];
    const float* Wk  = (const float*)d_in[2];
    const float* Wv  = (const float*)d_in[3];
    const float* Wo  = (const float*)d_in[4];
    const float* bo  = (const float*)d_in[5];
    const float* W1  = (const float*)d_in[6];
    const float* b1  = (const float*)d_in[7];
    const float* W2  = (const float*)d_in[8];
    const float* b2  = (const float*)d_in[9];
    const float* g1  = (const float*)d_in[10];
    const float* be1 = (const float*)d_in[11];
    const float* g2  = (const float*)d_in[12];
    const float* be2 = (const float*)d_in[13];
    float* out = (float*)d_out;

    float *nx, *qb, *kb, *vb, *ob, *x1, *nx2, *h1, *woT, *w1T, *w2T;
    cudaGetSymbolAddress((void**)&nx,  g_nx);
    cudaGetSymbolAddress((void**)&qb,  g_q);
    cudaGetSymbolAddress((void**)&kb,  g_k);
    cudaGetSymbolAddress((void**)&vb,  g_v);
    cudaGetSymbolAddress((void**)&ob,  g_o);
    cudaGetSymbolAddress((void**)&x1,  g_x1);
    cudaGetSymbolAddress((void**)&nx2, g_nx2);
    cudaGetSymbolAddress((void**)&h1,  g_h1);
    cudaGetSymbolAddress((void**)&woT, g_woT);
    cudaGetSymbolAddress((void**)&w1T, g_w1T);
    cudaGetSymbolAddress((void**)&w2T, g_w2T);

    cudaFuncSetAttribute(attn_kernel, cudaFuncAttributeMaxDynamicSharedMemorySize,
                         ATTN_SMEM_BYTES);
    cudaFuncSetAttribute(tgemm_kernel<0, 1, 0>, cudaFuncAttributeMaxDynamicSharedMemorySize,
                         GEMM_SMEM_BYTES);
    cudaFuncSetAttribute(tgemm_kernel<1, 0, 1>, cudaFuncAttributeMaxDynamicSharedMemorySize,
                         GEMM_SMEM_BYTES);

    // 0) transpose + tf32-round weights: W[K][N] -> Wt[N][K]
    transpose_tf32_kernel<<<dim3(E_ / 32, E_ / 32), dim3(32, 8)>>>(Wo, woT, E_, E_);
    transpose_tf32_kernel<<<dim3(F_ / 32, E_ / 32), dim3(32, 8)>>>(W1, w1T, E_, F_);
    transpose_tf32_kernel<<<dim3(E_ / 32, F_ / 32), dim3(32, 8)>>>(W2, w2T, F_, E_);
    // 1) LN1
    ln_kernel<0><<<TOK, 256>>>(x, g1, be1, nx);
    // 2) QKV projections
    qkv_kernel<<<dim3(S_ / 64, H_, B_), 256>>>(nx, Wq, Wk, Wv, qb, kb, vb);
    // 3) causal flash attention -> o (token-major, tf32-rounded)
    attn_kernel<<<dim3(S_ / 64, H_, B_), 256, ATTN_SMEM_BYTES>>>(qb, kb, vb, ob);
    // 4) x1 = x + o @ Wo + bo
    tgemm_kernel<0, 1, 0><<<dim3(E_ / BN, TOK / BM), 256, GEMM_SMEM_BYTES>>>(ob, woT, bo, x, x1, TOK, E_, E_);
    // 5) LN2 (tf32-rounded out)
    ln_kernel<1><<<TOK, 256>>>(x1, g2, be2, nx2);
    // 6) h1 = relu(nx2 @ W1 + b1), tf32-rounded out
    tgemm_kernel<1, 0, 1><<<dim3(F_ / BN, TOK / BM), 256, GEMM_SMEM_BYTES>>>(nx2, w1T, b1, nullptr, h1, TOK, F_, E_);
    // 7) out = x1 + h1 @ W2 + b2
    tgemm_kernel<0, 1, 0><<<dim3(E_ / BN, TOK / BM), 256, GEMM_SMEM_BYTES>>>(h1, w2T, b2, x1, out, TOK, E_, F_);
}

// round 8
// speedup vs baseline: 1.4888x; 1.4888x over previous
#include <cuda_runtime.h>
#include <cuda_fp16.h>
#include <math.h>
#include <stdint.h>

#define B_ 8
#define S_ 1024
#define E_ 1024
#define H_ 16
#define D_ 64
#define F_ 4096
#define TOK (B_ * S_)  // 8192

// ---------------- scratch (static device globals; no allocation) ----------------
__device__ float  g_nx [(size_t)TOK * E_];
__device__ float  g_q  [(size_t)TOK * E_];
__device__ float  g_k  [(size_t)TOK * E_];
__device__ float  g_v  [(size_t)TOK * E_];
__device__ __half g_o  [(size_t)TOK * E_];   // attention out (fp16, feeds Wo GEMM)
__device__ float  g_x1 [(size_t)TOK * E_];
__device__ __half g_nx2[(size_t)TOK * E_];   // LN2 out (fp16, feeds W1 GEMM)
__device__ __half g_h1 [(size_t)TOK * F_];   // MLP hidden (fp16, feeds W2 GEMM)
__device__ __half g_woT[(size_t)E_ * E_];    // Wo^T [N][K] fp16
__device__ __half g_w1T[(size_t)F_ * E_];    // W1^T [F][E] fp16
__device__ __half g_w2T[(size_t)E_ * F_];    // W2^T [E][F] fp16

// ---------------- helpers ----------------
__device__ __forceinline__ uint32_t f2tf32(float x) {
    uint32_t r;
    asm("cvt.rna.tf32.f32 %0, %1;" : "=r"(r) : "f"(x));
    return r;
}
__device__ __forceinline__ float f2tf32f(float x) {
    return __uint_as_float(f2tf32(x));
}
__device__ __forceinline__ void cp_async16(void* smem, const void* gmem) {
    uint32_t s = (uint32_t)__cvta_generic_to_shared(smem);
    asm volatile("cp.async.cg.shared.global [%0], [%1], 16;\n" :: "r"(s), "l"(gmem));
}
#define CP_COMMIT() asm volatile("cp.async.commit_group;\n" ::: "memory")
#define CP_WAIT0()  asm volatile("cp.async.wait_group 0;\n" ::: "memory")
#define CP_WAIT1()  asm volatile("cp.async.wait_group 1;\n" ::: "memory")

__device__ __forceinline__ void mma_tf32(float c[4], const uint32_t a[4], const uint32_t b[2]) {
    asm volatile(
        "mma.sync.aligned.m16n8k8.row.col.f32.tf32.tf32.f32 "
        "{%0,%1,%2,%3}, {%4,%5,%6,%7}, {%8,%9}, {%0,%1,%2,%3};\n"
        : "+f"(c[0]), "+f"(c[1]), "+f"(c[2]), "+f"(c[3])
        : "r"(a[0]), "r"(a[1]), "r"(a[2]), "r"(a[3]), "r"(b[0]), "r"(b[1]));
}
__device__ __forceinline__ void mma_f16(float c[4], const uint32_t a[4], const uint32_t b[2]) {
    asm volatile(
        "mma.sync.aligned.m16n8k16.row.col.f32.f16.f16.f32 "
        "{%0,%1,%2,%3}, {%4,%5,%6,%7}, {%8,%9}, {%0,%1,%2,%3};\n"
        : "+f"(c[0]), "+f"(c[1]), "+f"(c[2]), "+f"(c[3])
        : "r"(a[0]), "r"(a[1]), "r"(a[2]), "r"(a[3]), "r"(b[0]), "r"(b[1]));
}

// ---------------- weight transpose + fp16 round: in [K][N] f32 -> out [N][K] f16 ----------
__global__ __launch_bounds__(256) void transpose_h_kernel(const float* __restrict__ in,
                                                          __half* __restrict__ out,
                                                          int K, int N)
{
    __shared__ float tile[32][33];
    int bx = blockIdx.x;  // N / 32
    int by = blockIdx.y;  // K / 32
    int x = bx * 32 + threadIdx.x;           // n
    int y0 = by * 32 + threadIdx.y;          // k
#pragma unroll
    for (int j = 0; j < 32; j += 8)
        tile[threadIdx.y + j][threadIdx.x] = in[(size_t)(y0 + j) * N + x];
    __syncthreads();
    int xo = by * 32 + threadIdx.x;          // k
    int yo = bx * 32 + threadIdx.y;          // n
#pragma unroll
    for (int j = 0; j < 32; j += 8)
        out[(size_t)(yo + j) * K + xo] = __float2half_rn(tile[threadIdx.x][threadIdx.y + j]);
}

// ---------------- LayerNorm: one block per row of 1024 ----------------
template <int HALFOUT>
__global__ __launch_bounds__(256) void ln_kernel(const float* __restrict__ x,
                                                 const float* __restrict__ g,
                                                 const float* __restrict__ be,
                                                 void* __restrict__ out)
{
    int row = blockIdx.x;
    int tid = threadIdx.x;
    const float4* xr = reinterpret_cast<const float4*>(x + (size_t)row * E_);
    float4 a = xr[tid];
    float s  = a.x + a.y + a.z + a.w;
    float ss = a.x * a.x + a.y * a.y + a.z * a.z + a.w * a.w;
#pragma unroll
    for (int o = 16; o > 0; o >>= 1) {
        s  += __shfl_xor_sync(0xffffffffu, s,  o);
        ss += __shfl_xor_sync(0xffffffffu, ss, o);
    }
    __shared__ float sm[8], sm2[8];
    int w = tid >> 5, lane = tid & 31;
    if (lane == 0) { sm[w] = s; sm2[w] = ss; }
    __syncthreads();
    if (tid < 32) {
        s  = (tid < 8) ? sm[tid]  : 0.f;
        ss = (tid < 8) ? sm2[tid] : 0.f;
#pragma unroll
        for (int o = 4; o > 0; o >>= 1) {
            s  += __shfl_xor_sync(0xffffffffu, s,  o);
            ss += __shfl_xor_sync(0xffffffffu, ss, o);
        }
        if (tid == 0) { sm[0] = s; sm2[0] = ss; }
    }
    __syncthreads();
    float mean = sm[0] * (1.0f / E_);
    float var  = sm2[0] * (1.0f / E_) - mean * mean;
    float inv  = rsqrtf(var + 1e-5f);
    float4 gg = reinterpret_cast<const float4*>(g)[tid];
    float4 bb = reinterpret_cast<const float4*>(be)[tid];
    float4 o4;
    o4.x = (a.x - mean) * inv * gg.x + bb.x;
    o4.y = (a.y - mean) * inv * gg.y + bb.y;
    o4.z = (a.z - mean) * inv * gg.z + bb.z;
    o4.w = (a.w - mean) * inv * gg.w + bb.w;
    if (HALFOUT) {
        __half2* op = reinterpret_cast<__half2*>((__half*)out + (size_t)row * E_ + tid * 4);
        op[0] = __floats2half2_rn(o4.x, o4.y);
        op[1] = __floats2half2_rn(o4.z, o4.w);
    } else {
        reinterpret_cast<float4*>((float*)out + (size_t)row * E_)[tid] = o4;
    }
}

// ---------------- QKV projections: per (64-token tile, head, batch) ----------------
__global__ __launch_bounds__(256) void qkv_kernel(const float* __restrict__ nx,
                                                  const float* __restrict__ Wq,
                                                  const float* __restrict__ Wk,
                                                  const float* __restrict__ Wv,
                                                  float* __restrict__ q,
                                                  float* __restrict__ k,
                                                  float* __restrict__ v)
{
    int st = blockIdx.x, h = blockIdx.y, b = blockIdx.z;
    __shared__ float Xs[64][65];
    __shared__ float Ws[64][65];
    int tid = threadIdx.x;
    int tx = tid & 15, ty = tid >> 4;
#pragma unroll
    for (int it = 0; it < 4; it++) {
        int idx = tid + it * 256;
        int r = idx >> 4, c4 = (idx & 15) * 4;
        const float* src = nx + ((size_t)(b * S_ + st * 64 + r)) * E_ + h * 64 + c4;
        float4 a = *reinterpret_cast<const float4*>(src);
        Xs[r][c4] = a.x; Xs[r][c4 + 1] = a.y; Xs[r][c4 + 2] = a.z; Xs[r][c4 + 3] = a.w;
    }
    const float* Wm[3] = {Wq, Wk, Wv};
    float*       Om[3] = {q, k, v};
    size_t obase = ((size_t)(b * H_ + h) * S_ + st * 64) * D_;
#pragma unroll 1
    for (int m = 0; m < 3; m++) {
        __syncthreads();
#pragma unroll
        for (int it = 0; it < 4; it++) {
            int idx = tid + it * 256;
            int r = idx >> 4, c4 = (idx & 15) * 4;
            float4 a = *reinterpret_cast<const float4*>(Wm[m] + r * 64 + c4);
            Ws[r][c4] = a.x; Ws[r][c4 + 1] = a.y; Ws[r][c4 + 2] = a.z; Ws[r][c4 + 3] = a.w;
        }
        __syncthreads();
        float acc[4][4] = {};
#pragma unroll 4
        for (int d = 0; d < 64; d++) {
            float av[4], bv[4];
#pragma unroll
            for (int i = 0; i < 4; i++) av[i] = Xs[ty * 4 + i][d];
#pragma unroll
            for (int j = 0; j < 4; j++) bv[j] = Ws[d][tx * 4 + j];
#pragma unroll
            for (int i = 0; i < 4; i++)
#pragma unroll
                for (int j = 0; j < 4; j++)
                    acc[i][j] = fmaf(av[i], bv[j], acc[i][j]);
        }
        float* dst = Om[m] + obase;
#pragma unroll
        for (int i = 0; i < 4; i++) {
            float4 o4 = {acc[i][0], acc[i][1], acc[i][2], acc[i][3]};
            *reinterpret_cast<float4*>(dst + (ty * 4 + i) * 64 + tx * 4) = o4;
        }
    }
}

// ---------------- Causal flash attention, 64x64 tiles, mma.tf32; fp16 output ----------------
#define QSTR 68
#define KSTR 68
#define VSTR 72
#define PSTR 68
#define ATTN_SMEM_BYTES ((64 * (QSTR + KSTR + VSTR + PSTR)) * 4)

__global__ __launch_bounds__(256) void attn_kernel(const float* __restrict__ q,
                                                   const float* __restrict__ k,
                                                   const float* __restrict__ v,
                                                   __half* __restrict__ o)
{
    extern __shared__ float smem[];
    float* Qs = smem;
    float* Ks = Qs + 64 * QSTR;
    float* Vs = Ks + 64 * KSTR;
    float* Ps = Vs + 64 * VSTR;
    __shared__ float m_s[64], l_s[64], corr_s[64];

    int qt = blockIdx.x, h = blockIdx.y, b = blockIdx.z;
    int tid  = threadIdx.x;
    int lane = tid & 31, warp = tid >> 5;
    int wm = warp >> 1, wn = warp & 1;
    int m0 = wm * 16;
    int r4 = lane >> 2, c4 = lane & 3;
    int tx = tid & 15, ty = tid >> 4;
    const float scale = 0.03125f;
    size_t head_base = (size_t)(b * H_ + h) * S_ * D_;

#pragma unroll
    for (int it = 0; it < 4; it++) {
        int idx = tid + it * 256;
        int r = idx >> 4, c = (idx & 15) * 4;
        float4 a = *reinterpret_cast<const float4*>(q + head_base + (size_t)(qt * 64 + r) * 64 + c);
        float4 o4 = {f2tf32f(a.x * scale), f2tf32f(a.y * scale),
                     f2tf32f(a.z * scale), f2tf32f(a.w * scale)};
        *reinterpret_cast<float4*>(Qs + r * QSTR + c) = o4;
    }
    if (tid < 64) { m_s[tid] = -1e30f; l_s[tid] = 0.f; }

    float acc_o[4][4] = {};

    for (int kt = 0; kt <= qt; kt++) {
        __syncthreads();
#pragma unroll
        for (int it = 0; it < 4; it++) {
            int idx = tid + it * 256;
            int r = idx >> 4, c = (idx & 15) * 4;
            float4 a = *reinterpret_cast<const float4*>(k + head_base + (size_t)(kt * 64 + r) * 64 + c);
            float4 k4 = {f2tf32f(a.x), f2tf32f(a.y), f2tf32f(a.z), f2tf32f(a.w)};
            *reinterpret_cast<float4*>(Ks + r * KSTR + c) = k4;
            float4 bb = *reinterpret_cast<const float4*>(v + head_base + (size_t)(kt * 64 + r) * 64 + c);
            float4 v4 = {f2tf32f(bb.x), f2tf32f(bb.y), f2tf32f(bb.z), f2tf32f(bb.w)};
            *reinterpret_cast<float4*>(Vs + r * VSTR + c) = v4;
        }
        __syncthreads();

        float acc_s[4][4] = {};
#pragma unroll
        for (int ks = 0; ks < 8; ks++) {
            int kc = ks * 8;
            uint32_t a[4];
            a[0] = __float_as_uint(Qs[(m0 + r4) * QSTR + kc + c4]);
            a[1] = __float_as_uint(Qs[(m0 + r4 + 8) * QSTR + kc + c4]);
            a[2] = __float_as_uint(Qs[(m0 + r4) * QSTR + kc + c4 + 4]);
            a[3] = __float_as_uint(Qs[(m0 + r4 + 8) * QSTR + kc + c4 + 4]);
#pragma unroll
            for (int ni = 0; ni < 4; ni++) {
                int n0 = wn * 32 + ni * 8;
                uint32_t bf[2];
                bf[0] = __float_as_uint(Ks[(n0 + r4) * KSTR + kc + c4]);
                bf[1] = __float_as_uint(Ks[(n0 + r4) * KSTR + kc + c4 + 4]);
                mma_tf32(acc_s[ni], a, bf);
            }
        }
#pragma unroll
        for (int ni = 0; ni < 4; ni++) {
            int n0 = wn * 32 + ni * 8 + 2 * c4;
            *reinterpret_cast<float2*>(Ps + (m0 + r4) * PSTR + n0) =
                make_float2(acc_s[ni][0], acc_s[ni][1]);
            *reinterpret_cast<float2*>(Ps + (m0 + r4 + 8) * PSTR + n0) =
                make_float2(acc_s[ni][2], acc_s[ni][3]);
        }
        __syncthreads();

        bool diag = (kt == qt);
#pragma unroll
        for (int i = 0; i < 4; i++) {
            int r = ty * 4 + i;
            float4 s4 = *reinterpret_cast<float4*>(Ps + r * PSTR + tx * 4);
            float sv[4] = {s4.x, s4.y, s4.z, s4.w};
            if (diag) {
#pragma unroll
                for (int j = 0; j < 4; j++)
                    if (tx * 4 + j > r) sv[j] = -1e30f;
            }
            float mm = fmaxf(fmaxf(sv[0], sv[1]), fmaxf(sv[2], sv[3]));
#pragma unroll
            for (int off = 8; off > 0; off >>= 1)
                mm = fmaxf(mm, __shfl_xor_sync(0xffffffffu, mm, off, 16));
            float mo = m_s[r];
            float mn = fmaxf(mo, mm);
            float corr = expf(mo - mn);
            float e0 = expf(sv[0] - mn), e1 = expf(sv[1] - mn);
            float e2 = expf(sv[2] - mn), e3 = expf(sv[3] - mn);
            float rs = e0 + e1 + e2 + e3;
            float4 p4 = {f2tf32f(e0), f2tf32f(e1), f2tf32f(e2), f2tf32f(e3)};
            *reinterpret_cast<float4*>(Ps + r * PSTR + tx * 4) = p4;
#pragma unroll
            for (int off = 8; off > 0; off >>= 1)
                rs += __shfl_xor_sync(0xffffffffu, rs, off, 16);
            if (tx == 0) { m_s[r] = mn; l_s[r] = l_s[r] * corr + rs; corr_s[r] = corr; }
        }
        __syncthreads();

        float cr0 = corr_s[m0 + r4];
        float cr1 = corr_s[m0 + r4 + 8];
#pragma unroll
        for (int ni = 0; ni < 4; ni++) {
            acc_o[ni][0] *= cr0; acc_o[ni][1] *= cr0;
            acc_o[ni][2] *= cr1; acc_o[ni][3] *= cr1;
        }
#pragma unroll
        for (int ks = 0; ks < 8; ks++) {
            int kc = ks * 8;
            uint32_t a[4];
            a[0] = __float_as_uint(Ps[(m0 + r4) * PSTR + kc + c4]);
            a[1] = __float_as_uint(Ps[(m0 + r4 + 8) * PSTR + kc + c4]);
            a[2] = __float_as_uint(Ps[(m0 + r4) * PSTR + kc + c4 + 4]);
            a[3] = __float_as_uint(Ps[(m0 + r4 + 8) * PSTR + kc + c4 + 4]);
#pragma unroll
            for (int ni = 0; ni < 4; ni++) {
                int n0 = wn * 32 + ni * 8;
                uint32_t bf[2];
                bf[0] = __float_as_uint(Vs[(kc + c4) * VSTR + n0 + r4]);
                bf[1] = __float_as_uint(Vs[(kc + c4 + 4) * VSTR + n0 + r4]);
                mma_tf32(acc_o[ni], a, bf);
            }
        }
    }

    // epilogue: normalize, fp16 round, token-major [B,S,H,D]
    float inv0 = 1.0f / l_s[m0 + r4];
    float inv1 = 1.0f / l_s[m0 + r4 + 8];
    __half* ob = o + ((size_t)(b * S_ + qt * 64)) * E_ + h * 64;
#pragma unroll
    for (int ni = 0; ni < 4; ni++) {
        int cc = wn * 32 + ni * 8 + 2 * c4;
        *reinterpret_cast<__half2*>(ob + (size_t)(m0 + r4) * E_ + cc) =
            __floats2half2_rn(acc_o[ni][0] * inv0, acc_o[ni][1] * inv0);
        *reinterpret_cast<__half2*>(ob + (size_t)(m0 + r4 + 8) * E_ + cc) =
            __floats2half2_rn(acc_o[ni][2] * inv1, acc_o[ni][3] * inv1);
    }
}

// ---------------- FP16 tensor-core GEMM: 128x128x32, mma.m16n8k16, 3-stage cp.async ------
// A [M][K] f16 K-major; Bt [N][K] f16 K-major. C = A@Bt^T + bias (+relu)(+resid); C f32 or f16.
#define BM 128
#define BN 128
#define BKH 32                        // K halves per tile
#define HSTR 40                       // BKH + 8 pad (80B rows, conflict-free half2 frags)
#define H_STAGE (BM * HSTR)           // halves per operand stage (5120)
#define GEMM_SMEM_BYTES (6 * H_STAGE * 2)   // 61440

template <int RELU, int RES, int HALFOUT>
__global__ __launch_bounds__(256) void hgemm_kernel(const __half* __restrict__ A,
                                                    const __half* __restrict__ Bt,
                                                    const float* __restrict__ bias,
                                                    const float* __restrict__ resid,
                                                    void* __restrict__ Cout,
                                                    int M, int N, int K)
{
    extern __shared__ __half shh[];
    __half* Asm = shh;                   // [3][BM][HSTR]
    __half* Bsm = shh + 3 * H_STAGE;     // [3][BN][HSTR]

    const int tid  = threadIdx.x;
    const int lane = tid & 31;
    const int warp = tid >> 5;
    const int wm = warp >> 2;          // 0..1
    const int wn = warp & 3;           // 0..3
    const int m_w = wm * 64;
    const int n_w = wn * 32;
    const int r4 = lane >> 2;          // 0..7
    const int c4 = lane & 3;           // 0..3
    const int bx = blockIdx.x, by = blockIdx.y;

    const __half* Ab = A  + (size_t)by * BM * K;
    const __half* Bb = Bt + (size_t)bx * BN * K;

    auto load_tile = [&](int buf, int k0) {
        __half* Ad = Asm + buf * H_STAGE;
        __half* Bd = Bsm + buf * H_STAGE;
#pragma unroll
        for (int i = 0; i < 2; i++) {
            int idx = tid + i * 256;
            int row = idx >> 2, kq = (idx & 3) * 8;
            cp_async16(Ad + row * HSTR + kq, Ab + (size_t)row * K + k0 + kq);
        }
#pragma unroll
        for (int i = 0; i < 2; i++) {
            int idx = tid + i * 256;
            int row = idx >> 2, kq = (idx & 3) * 8;
            cp_async16(Bd + row * HSTR + kq, Bb + (size_t)row * K + k0 + kq);
        }
        CP_COMMIT();
    };

    float acc[4][4][4] = {};

    const int nT = K / BKH;
    load_tile(0, 0);
    load_tile(1, BKH);

#pragma unroll 1
    for (int t = 0; t < nT; t++) {
        if (t + 1 < nT) { CP_WAIT1(); } else { CP_WAIT0(); }
        __syncthreads();
        if (t + 2 < nT) load_tile((t + 2) % 3, (t + 2) * BKH);

        const __half* Ac = Asm + (t % 3) * H_STAGE;
        const __half* Bc = Bsm + (t % 3) * H_STAGE;
#pragma unroll
        for (int ks = 0; ks < 2; ks++) {
            const int kc = ks * 16;
            uint32_t a[4][4], b[4][2];
#pragma unroll
            for (int mi = 0; mi < 4; mi++) {
                int m0 = m_w + mi * 16;
                a[mi][0] = *reinterpret_cast<const uint32_t*>(Ac + (m0 + r4) * HSTR + kc + 2 * c4);
                a[mi][1] = *reinterpret_cast<const uint32_t*>(Ac + (m0 + r4 + 8) * HSTR + kc + 2 * c4);
                a[mi][2] = *reinterpret_cast<const uint32_t*>(Ac + (m0 + r4) * HSTR + kc + 2 * c4 + 8);
                a[mi][3] = *reinterpret_cast<const uint32_t*>(Ac + (m0 + r4 + 8) * HSTR + kc + 2 * c4 + 8);
            }
#pragma unroll
            for (int ni = 0; ni < 4; ni++) {
                int n0 = n_w + ni * 8;
                b[ni][0] = *reinterpret_cast<const uint32_t*>(Bc + (n0 + r4) * HSTR + kc + 2 * c4);
                b[ni][1] = *reinterpret_cast<const uint32_t*>(Bc + (n0 + r4) * HSTR + kc + 2 * c4 + 8);
            }
#pragma unroll
            for (int mi = 0; mi < 4; mi++)
#pragma unroll
                for (int ni = 0; ni < 4; ni++)
                    mma_f16(acc[mi][ni], a[mi], b[ni]);
        }
        // no trailing sync: leading sync next iter orders buffer reuse
    }

    // epilogue
    const int row_base = by * BM + m_w;
    const int col_base = bx * BN + n_w;
#pragma unroll
    for (int mi = 0; mi < 4; mi++) {
#pragma unroll
        for (int ni = 0; ni < 4; ni++) {
            int c0 = col_base + ni * 8 + 2 * c4;
            float2 bb = *reinterpret_cast<const float2*>(bias + c0);
#pragma unroll
            for (int half = 0; half < 2; half++) {
                int r0 = row_base + mi * 16 + r4 + half * 8;
                float v0 = acc[mi][ni][half * 2]     + bb.x;
                float v1 = acc[mi][ni][half * 2 + 1] + bb.y;
                if (RELU) { v0 = fmaxf(v0, 0.f); v1 = fmaxf(v1, 0.f); }
                if (RES) {
                    float2 rr = *reinterpret_cast<const float2*>(resid + (size_t)r0 * N + c0);
                    v0 += rr.x; v1 += rr.y;
                }
                if (HALFOUT) {
                    *reinterpret_cast<__half2*>((__half*)Cout + (size_t)r0 * N + c0) =
                        __floats2half2_rn(v0, v1);
                } else {
                    float2 o2 = {v0, v1};
                    *reinterpret_cast<float2*>((float*)Cout + (size_t)r0 * N + c0) = o2;
                }
            }
        }
    }
}

// ---------------- launch ----------------
extern "C" void kernel_launch(void* const* d_in, const int* in_sizes, int n_in,
                              void* d_out, int out_size)
{
    (void)in_sizes; (void)n_in; (void)out_size;
    const float* x   = (const float*)d_in[0];
    const float* Wq  = (const float*)d_in[1];
    const float* Wk  = (const float*)d_in[2];
    const float* Wv  = (const float*)d_in[3];
    const float* Wo  = (const float*)d_in[4];
    const float* bo  = (const float*)d_in[5];
    const float* W1  = (const float*)d_in[6];
    const float* b1  = (const float*)d_in[7];
    const float* W2  = (const float*)d_in[8];
    const float* b2  = (const float*)d_in[9];
    const float* g1  = (const float*)d_in[10];
    const float* be1 = (const float*)d_in[11];
    const float* g2  = (const float*)d_in[12];
    const float* be2 = (const float*)d_in[13];
    float* out = (float*)d_out;

    float *nx, *qb, *kb, *vb, *x1;
    __half *ob, *nx2, *h1, *woT, *w1T, *w2T;
    cudaGetSymbolAddress((void**)&nx,  g_nx);
    cudaGetSymbolAddress((void**)&qb,  g_q);
    cudaGetSymbolAddress((void**)&kb,  g_k);
    cudaGetSymbolAddress((void**)&vb,  g_v);
    cudaGetSymbolAddress((void**)&ob,  g_o);
    cudaGetSymbolAddress((void**)&x1,  g_x1);
    cudaGetSymbolAddress((void**)&nx2, g_nx2);
    cudaGetSymbolAddress((void**)&h1,  g_h1);
    cudaGetSymbolAddress((void**)&woT, g_woT);
    cudaGetSymbolAddress((void**)&w1T, g_w1T);
    cudaGetSymbolAddress((void**)&w2T, g_w2T);

    cudaFuncSetAttribute(attn_kernel, cudaFuncAttributeMaxDynamicSharedMemorySize,
                         ATTN_SMEM_BYTES);
    cudaFuncSetAttribute(hgemm_kernel<0, 1, 0>, cudaFuncAttributeMaxDynamicSharedMemorySize,
                         GEMM_SMEM_BYTES);
    cudaFuncSetAttribute(hgemm_kernel<1, 0, 1>, cudaFuncAttributeMaxDynamicSharedMemorySize,
                         GEMM_SMEM_BYTES);

    // 0) transpose + fp16 weights: W[K][N] -> Wt[N][K]
    transpose_h_kernel<<<dim3(E_ / 32, E_ / 32), dim3(32, 8)>>>(Wo, woT, E_, E_);
    transpose_h_kernel<<<dim3(F_ / 32, E_ / 32), dim3(32, 8)>>>(W1, w1T, E_, F_);
    transpose_h_kernel<<<dim3(E_ / 32, F_ / 32), dim3(32, 8)>>>(W2, w2T, F_, E_);
    // 1) LN1 (f32 out)
    ln_kernel<0><<<TOK, 256>>>(x, g1, be1, nx);
    // 2) QKV projections
    qkv_kernel<<<dim3(S_ / 64, H_, B_), 256>>>(nx, Wq, Wk, Wv, qb, kb, vb);
    // 3) causal flash attention -> o (token-major, fp16)
    attn_kernel<<<dim3(S_ / 64, H_, B_), 256, ATTN_SMEM_BYTES>>>(qb, kb, vb, ob);
    // 4) x1 = x + o @ Wo + bo   (f32 out)
    hgemm_kernel<0, 1, 0><<<dim3(E_ / BN, TOK / BM), 256, GEMM_SMEM_BYTES>>>(ob, woT, bo, x, x1, TOK, E_, E_);
    // 5) LN2 (fp16 out)
    ln_kernel<1><<<TOK, 256>>>(x1, g2, be2, nx2);
    // 6) h1 = relu(nx2 @ W1 + b1)  (fp16 out)
    hgemm_kernel<1, 0, 1><<<dim3(F_ / BN, TOK / BM), 256, GEMM_SMEM_BYTES>>>(nx2, w1T, b1, nullptr, h1, TOK, F_, E_);
    // 7) out = x1 + h1 @ W2 + b2   (f32 out)
    hgemm_kernel<0, 1, 0><<<dim3(E_ / BN, TOK / BM), 256, GEMM_SMEM_BYTES>>>(h1, w2T, b2, x1, out, TOK, E_, F_);
}

// round 9
// speedup vs baseline: 1.4981x; 1.0063x over previous
#include <cuda_runtime.h>
#include <cuda_fp16.h>
#include <math.h>
#include <stdint.h>

#define B_ 8
#define S_ 1024
#define E_ 1024
#define H_ 16
#define D_ 64
#define F_ 4096
#define TOK (B_ * S_)  // 8192

// ---------------- scratch (static device globals; no allocation) ----------------
__device__ float  g_nx [(size_t)TOK * E_];
__device__ __half g_q  [(size_t)TOK * E_];
__device__ __half g_k  [(size_t)TOK * E_];
__device__ __half g_v  [(size_t)TOK * E_];
__device__ __half g_o  [(size_t)TOK * E_];
__device__ float  g_x1 [(size_t)TOK * E_];
__device__ __half g_nx2[(size_t)TOK * E_];
__device__ __half g_h1 [(size_t)TOK * F_];
__device__ __half g_woT[(size_t)E_ * E_];
__device__ __half g_w1T[(size_t)F_ * E_];
__device__ __half g_w2T[(size_t)E_ * F_];

// ---------------- helpers ----------------
__device__ __forceinline__ void cp_async16(void* smem, const void* gmem) {
    uint32_t s = (uint32_t)__cvta_generic_to_shared(smem);
    asm volatile("cp.async.cg.shared.global [%0], [%1], 16;\n" :: "r"(s), "l"(gmem));
}
#define CP_COMMIT() asm volatile("cp.async.commit_group;\n" ::: "memory")
#define CP_WAIT0()  asm volatile("cp.async.wait_group 0;\n" ::: "memory")
#define CP_WAIT1()  asm volatile("cp.async.wait_group 1;\n" ::: "memory")

__device__ __forceinline__ void mma_f16(float c[4], const uint32_t a[4], const uint32_t b[2]) {
    asm volatile(
        "mma.sync.aligned.m16n8k16.row.col.f32.f16.f16.f32 "
        "{%0,%1,%2,%3}, {%4,%5,%6,%7}, {%8,%9}, {%0,%1,%2,%3};\n"
        : "+f"(c[0]), "+f"(c[1]), "+f"(c[2]), "+f"(c[3])
        : "r"(a[0]), "r"(a[1]), "r"(a[2]), "r"(a[3]), "r"(b[0]), "r"(b[1]));
}

// ---------------- weight transpose + fp16 round: in [K][N] f32 -> out [N][K] f16 ----------
__global__ __launch_bounds__(256) void transpose_h_kernel(const float* __restrict__ in,
                                                          __half* __restrict__ out,
                                                          int K, int N)
{
    __shared__ float tile[32][33];
    int bx = blockIdx.x;
    int by = blockIdx.y;
    int x = bx * 32 + threadIdx.x;
    int y0 = by * 32 + threadIdx.y;
#pragma unroll
    for (int j = 0; j < 32; j += 8)
        tile[threadIdx.y + j][threadIdx.x] = in[(size_t)(y0 + j) * N + x];
    __syncthreads();
    int xo = by * 32 + threadIdx.x;
    int yo = bx * 32 + threadIdx.y;
#pragma unroll
    for (int j = 0; j < 32; j += 8)
        out[(size_t)(yo + j) * K + xo] = __float2half_rn(tile[threadIdx.x][threadIdx.y + j]);
}

// ---------------- LayerNorm: one block per row of 1024 ----------------
template <int HALFOUT>
__global__ __launch_bounds__(256) void ln_kernel(const float* __restrict__ x,
                                                 const float* __restrict__ g,
                                                 const float* __restrict__ be,
                                                 void* __restrict__ out)
{
    int row = blockIdx.x;
    int tid = threadIdx.x;
    const float4* xr = reinterpret_cast<const float4*>(x + (size_t)row * E_);
    float4 a = xr[tid];
    float s  = a.x + a.y + a.z + a.w;
    float ss = a.x * a.x + a.y * a.y + a.z * a.z + a.w * a.w;
#pragma unroll
    for (int o = 16; o > 0; o >>= 1) {
        s  += __shfl_xor_sync(0xffffffffu, s,  o);
        ss += __shfl_xor_sync(0xffffffffu, ss, o);
    }
    __shared__ float sm[8], sm2[8];
    int w = tid >> 5, lane = tid & 31;
    if (lane == 0) { sm[w] = s; sm2[w] = ss; }
    __syncthreads();
    if (tid < 32) {
        s  = (tid < 8) ? sm[tid]  : 0.f;
        ss = (tid < 8) ? sm2[tid] : 0.f;
#pragma unroll
        for (int o = 4; o > 0; o >>= 1) {
            s  += __shfl_xor_sync(0xffffffffu, s,  o);
            ss += __shfl_xor_sync(0xffffffffu, ss, o);
        }
        if (tid == 0) { sm[0] = s; sm2[0] = ss; }
    }
    __syncthreads();
    float mean = sm[0] * (1.0f / E_);
    float var  = sm2[0] * (1.0f / E_) - mean * mean;
    float inv  = rsqrtf(var + 1e-5f);
    float4 gg = reinterpret_cast<const float4*>(g)[tid];
    float4 bb = reinterpret_cast<const float4*>(be)[tid];
    float4 o4;
    o4.x = (a.x - mean) * inv * gg.x + bb.x;
    o4.y = (a.y - mean) * inv * gg.y + bb.y;
    o4.z = (a.z - mean) * inv * gg.z + bb.z;
    o4.w = (a.w - mean) * inv * gg.w + bb.w;
    if (HALFOUT) {
        __half2* op = reinterpret_cast<__half2*>((__half*)out + (size_t)row * E_ + tid * 4);
        op[0] = __floats2half2_rn(o4.x, o4.y);
        op[1] = __floats2half2_rn(o4.z, o4.w);
    } else {
        reinterpret_cast<float4*>((float*)out + (size_t)row * E_)[tid] = o4;
    }
}

// ---------------- QKV projections -> fp16 [B,H,S,D] ----------------
__global__ __launch_bounds__(256) void qkv_kernel(const float* __restrict__ nx,
                                                  const float* __restrict__ Wq,
                                                  const float* __restrict__ Wk,
                                                  const float* __restrict__ Wv,
                                                  __half* __restrict__ q,
                                                  __half* __restrict__ k,
                                                  __half* __restrict__ v)
{
    int st = blockIdx.x, h = blockIdx.y, b = blockIdx.z;
    __shared__ float Xs[64][65];
    __shared__ float Ws[64][65];
    int tid = threadIdx.x;
    int tx = tid & 15, ty = tid >> 4;
#pragma unroll
    for (int it = 0; it < 4; it++) {
        int idx = tid + it * 256;
        int r = idx >> 4, c4 = (idx & 15) * 4;
        const float* src = nx + ((size_t)(b * S_ + st * 64 + r)) * E_ + h * 64 + c4;
        float4 a = *reinterpret_cast<const float4*>(src);
        Xs[r][c4] = a.x; Xs[r][c4 + 1] = a.y; Xs[r][c4 + 2] = a.z; Xs[r][c4 + 3] = a.w;
    }
    const float* Wm[3] = {Wq, Wk, Wv};
    __half*      Om[3] = {q, k, v};
    size_t obase = ((size_t)(b * H_ + h) * S_ + st * 64) * D_;
#pragma unroll 1
    for (int m = 0; m < 3; m++) {
        __syncthreads();
#pragma unroll
        for (int it = 0; it < 4; it++) {
            int idx = tid + it * 256;
            int r = idx >> 4, c4 = (idx & 15) * 4;
            float4 a = *reinterpret_cast<const float4*>(Wm[m] + r * 64 + c4);
            Ws[r][c4] = a.x; Ws[r][c4 + 1] = a.y; Ws[r][c4 + 2] = a.z; Ws[r][c4 + 3] = a.w;
        }
        __syncthreads();
        float acc[4][4] = {};
#pragma unroll 4
        for (int d = 0; d < 64; d++) {
            float av[4], bv[4];
#pragma unroll
            for (int i = 0; i < 4; i++) av[i] = Xs[ty * 4 + i][d];
#pragma unroll
            for (int j = 0; j < 4; j++) bv[j] = Ws[d][tx * 4 + j];
#pragma unroll
            for (int i = 0; i < 4; i++)
#pragma unroll
                for (int j = 0; j < 4; j++)
                    acc[i][j] = fmaf(av[i], bv[j], acc[i][j]);
        }
        __half* dst = Om[m] + obase;
#pragma unroll
        for (int i = 0; i < 4; i++) {
            __half2* dp = reinterpret_cast<__half2*>(dst + (ty * 4 + i) * 64 + tx * 4);
            dp[0] = __floats2half2_rn(acc[i][0], acc[i][1]);
            dp[1] = __floats2half2_rn(acc[i][2], acc[i][3]);
        }
    }
}

// ---------------- Causal flash attention, 64x64 tiles, fp16 mma.m16n8k16 ----------------
// smem strides in halves; 72 -> fragment bank = 4*r4+c4 pattern, conflict-free.
#define AH_STR 72
#define SF_STR 68
#define ATTN_SMEM_BYTES ((4 * 64 * AH_STR) * 2 + (64 * SF_STR) * 4)

__global__ __launch_bounds__(256) void attn_kernel(const __half* __restrict__ q,
                                                   const __half* __restrict__ k,
                                                   const __half* __restrict__ v,
                                                   __half* __restrict__ o)
{
    extern __shared__ char asm_[];
    __half* Qh = reinterpret_cast<__half*>(asm_);                 // [64][72]
    __half* Kh = Qh + 64 * AH_STR;                                // [64][72]
    __half* Vt = Kh + 64 * AH_STR;                                // [64][72] d-major
    __half* Ph = Vt + 64 * AH_STR;                                // [64][72]
    float*  Sf = reinterpret_cast<float*>(Ph + 64 * AH_STR);      // [64][68]
    __shared__ float m_s[64], l_s[64], corr_s[64];

    int qt = blockIdx.x, h = blockIdx.y, b = blockIdx.z;
    int tid  = threadIdx.x;
    int lane = tid & 31, warp = tid >> 5;
    int wm = warp >> 1, wn = warp & 1;
    int m0 = wm * 16;
    int r4 = lane >> 2, c4 = lane & 3;
    int tx = tid & 15, ty = tid >> 4;
    size_t head_base = (size_t)(b * H_ + h) * S_ * D_;
    const __half2 hscale = __float2half2_rn(0.03125f);  // 1/32, exact in fp16

    // load Q (scaled)
#pragma unroll
    for (int it = 0; it < 2; it++) {
        int idx = tid + it * 256;
        int r = idx >> 3, c8 = (idx & 7) * 8;
        uint4 raw = *reinterpret_cast<const uint4*>(q + head_base + (size_t)(qt * 64 + r) * 64 + c8);
        __half2* hp = reinterpret_cast<__half2*>(&raw);
#pragma unroll
        for (int j = 0; j < 4; j++) hp[j] = __hmul2(hp[j], hscale);
        *reinterpret_cast<uint4*>(Qh + r * AH_STR + c8) = raw;
    }
    if (tid < 64) { m_s[tid] = -1e30f; l_s[tid] = 0.f; }

    float acc_o[4][4] = {};

    for (int kt = 0; kt <= qt; kt++) {
        __syncthreads();
        // K: direct copy; V: transpose to Vt[d][s]
#pragma unroll
        for (int it = 0; it < 2; it++) {
            int idx = tid + it * 256;
            int r = idx >> 3, c8 = (idx & 7) * 8;
            uint4 kraw = *reinterpret_cast<const uint4*>(k + head_base + (size_t)(kt * 64 + r) * 64 + c8);
            *reinterpret_cast<uint4*>(Kh + r * AH_STR + c8) = kraw;
            uint4 vraw = *reinterpret_cast<const uint4*>(v + head_base + (size_t)(kt * 64 + r) * 64 + c8);
            const __half* vh = reinterpret_cast<const __half*>(&vraw);
#pragma unroll
            for (int j = 0; j < 8; j++) Vt[(c8 + j) * AH_STR + r] = vh[j];
        }
        __syncthreads();

        // ---- S = Q @ K^T ----
        float acc_s[4][4] = {};
#pragma unroll
        for (int ks = 0; ks < 4; ks++) {
            int kc = ks * 16;
            uint32_t a[4];
            a[0] = *reinterpret_cast<const uint32_t*>(Qh + (m0 + r4) * AH_STR + kc + 2 * c4);
            a[1] = *reinterpret_cast<const uint32_t*>(Qh + (m0 + r4 + 8) * AH_STR + kc + 2 * c4);
            a[2] = *reinterpret_cast<const uint32_t*>(Qh + (m0 + r4) * AH_STR + kc + 2 * c4 + 8);
            a[3] = *reinterpret_cast<const uint32_t*>(Qh + (m0 + r4 + 8) * AH_STR + kc + 2 * c4 + 8);
#pragma unroll
            for (int ni = 0; ni < 4; ni++) {
                int n0 = wn * 32 + ni * 8;
                uint32_t bf[2];
                bf[0] = *reinterpret_cast<const uint32_t*>(Kh + (n0 + r4) * AH_STR + kc + 2 * c4);
                bf[1] = *reinterpret_cast<const uint32_t*>(Kh + (n0 + r4) * AH_STR + kc + 2 * c4 + 8);
                mma_f16(acc_s[ni], a, bf);
            }
        }
        // store S (fp32) for softmax
#pragma unroll
        for (int ni = 0; ni < 4; ni++) {
            int n0 = wn * 32 + ni * 8 + 2 * c4;
            *reinterpret_cast<float2*>(Sf + (m0 + r4) * SF_STR + n0) =
                make_float2(acc_s[ni][0], acc_s[ni][1]);
            *reinterpret_cast<float2*>(Sf + (m0 + r4 + 8) * SF_STR + n0) =
                make_float2(acc_s[ni][2], acc_s[ni][3]);
        }
        __syncthreads();

        // ---- online softmax (rows ty*4..+3, cols tx*4..+3) ----
        bool diag = (kt == qt);
#pragma unroll
        for (int i = 0; i < 4; i++) {
            int r = ty * 4 + i;
            float4 s4 = *reinterpret_cast<float4*>(Sf + r * SF_STR + tx * 4);
            float sv[4] = {s4.x, s4.y, s4.z, s4.w};
            if (diag) {
#pragma unroll
                for (int j = 0; j < 4; j++)
                    if (tx * 4 + j > r) sv[j] = -1e30f;
            }
            float mm = fmaxf(fmaxf(sv[0], sv[1]), fmaxf(sv[2], sv[3]));
#pragma unroll
            for (int off = 8; off > 0; off >>= 1)
                mm = fmaxf(mm, __shfl_xor_sync(0xffffffffu, mm, off, 16));
            float mo = m_s[r];
            float mn = fmaxf(mo, mm);
            float corr = expf(mo - mn);
            float e0 = expf(sv[0] - mn), e1 = expf(sv[1] - mn);
            float e2 = expf(sv[2] - mn), e3 = expf(sv[3] - mn);
            float rs = e0 + e1 + e2 + e3;
            __half2* pp = reinterpret_cast<__half2*>(Ph + r * AH_STR + tx * 4);
            pp[0] = __floats2half2_rn(e0, e1);
            pp[1] = __floats2half2_rn(e2, e3);
#pragma unroll
            for (int off = 8; off > 0; off >>= 1)
                rs += __shfl_xor_sync(0xffffffffu, rs, off, 16);
            if (tx == 0) { m_s[r] = mn; l_s[r] = l_s[r] * corr + rs; corr_s[r] = corr; }
        }
        __syncthreads();

        // ---- O = O*corr + P @ V ----
        float cr0 = corr_s[m0 + r4];
        float cr1 = corr_s[m0 + r4 + 8];
#pragma unroll
        for (int ni = 0; ni < 4; ni++) {
            acc_o[ni][0] *= cr0; acc_o[ni][1] *= cr0;
            acc_o[ni][2] *= cr1; acc_o[ni][3] *= cr1;
        }
#pragma unroll
        for (int ks = 0; ks < 4; ks++) {
            int kc = ks * 16;
            uint32_t a[4];
            a[0] = *reinterpret_cast<const uint32_t*>(Ph + (m0 + r4) * AH_STR + kc + 2 * c4);
            a[1] = *reinterpret_cast<const uint32_t*>(Ph + (m0 + r4 + 8) * AH_STR + kc + 2 * c4);
            a[2] = *reinterpret_cast<const uint32_t*>(Ph + (m0 + r4) * AH_STR + kc + 2 * c4 + 8);
            a[3] = *reinterpret_cast<const uint32_t*>(Ph + (m0 + r4 + 8) * AH_STR + kc + 2 * c4 + 8);
#pragma unroll
            for (int ni = 0; ni < 4; ni++) {
                int n0 = wn * 32 + ni * 8;   // d-dim
                uint32_t bf[2];
                bf[0] = *reinterpret_cast<const uint32_t*>(Vt + (n0 + r4) * AH_STR + kc + 2 * c4);
                bf[1] = *reinterpret_cast<const uint32_t*>(Vt + (n0 + r4) * AH_STR + kc + 2 * c4 + 8);
                mma_f16(acc_o[ni], a, bf);
            }
        }
    }

    // epilogue: normalize, fp16, token-major [B,S,H,D]
    float inv0 = 1.0f / l_s[m0 + r4];
    float inv1 = 1.0f / l_s[m0 + r4 + 8];
    __half* ob = o + ((size_t)(b * S_ + qt * 64)) * E_ + h * 64;
#pragma unroll
    for (int ni = 0; ni < 4; ni++) {
        int cc = wn * 32 + ni * 8 + 2 * c4;
        *reinterpret_cast<__half2*>(ob + (size_t)(m0 + r4) * E_ + cc) =
            __floats2half2_rn(acc_o[ni][0] * inv0, acc_o[ni][1] * inv0);
        *reinterpret_cast<__half2*>(ob + (size_t)(m0 + r4 + 8) * E_ + cc) =
            __floats2half2_rn(acc_o[ni][2] * inv1, acc_o[ni][3] * inv1);
    }
}

// ---------------- FP16 GEMM: 128x256x32 tiles, warp 64x64, 3-stage cp.async ------------
#define BM 128
#define BN 256
#define BKH 32
#define HSTR 40
#define A_STG (BM * HSTR)             // 5120 halves
#define B_STG (BN * HSTR)             // 10240 halves
#define GEMM_SMEM_BYTES (3 * (A_STG + B_STG) * 2)   // 92160

template <int RELU, int RES, int HALFOUT>
__global__ __launch_bounds__(256) void hgemm_kernel(const __half* __restrict__ A,
                                                    const __half* __restrict__ Bt,
                                                    const float* __restrict__ bias,
                                                    const float* __restrict__ resid,
                                                    void* __restrict__ Cout,
                                                    int M, int N, int K)
{
    extern __shared__ __half shh[];
    __half* Asm = shh;                   // [3][BM][HSTR]
    __half* Bsm = shh + 3 * A_STG;       // [3][BN][HSTR]

    const int tid  = threadIdx.x;
    const int lane = tid & 31;
    const int warp = tid >> 5;
    const int wm = warp >> 2;          // 0..1
    const int wn = warp & 3;           // 0..3
    const int m_w = wm * 64;
    const int n_w = wn * 64;
    const int r4 = lane >> 2;
    const int c4 = lane & 3;
    const int bx = blockIdx.x, by = blockIdx.y;

    const __half* Ab = A  + (size_t)by * BM * K;
    const __half* Bb = Bt + (size_t)bx * BN * K;

    auto load_tile = [&](int buf, int k0) {
        __half* Ad = Asm + buf * A_STG;
        __half* Bd = Bsm + buf * B_STG;
#pragma unroll
        for (int i = 0; i < 2; i++) {
            int idx = tid + i * 256;
            int row = idx >> 2, kq = (idx & 3) * 8;
            cp_async16(Ad + row * HSTR + kq, Ab + (size_t)row * K + k0 + kq);
        }
#pragma unroll
        for (int i = 0; i < 4; i++) {
            int idx = tid + i * 256;
            int row = idx >> 2, kq = (idx & 3) * 8;
            cp_async16(Bd + row * HSTR + kq, Bb + (size_t)row * K + k0 + kq);
        }
        CP_COMMIT();
    };

    float acc[4][8][4] = {};

    const int nT = K / BKH;
    load_tile(0, 0);
    load_tile(1, BKH);

#pragma unroll 1
    for (int t = 0; t < nT; t++) {
        if (t + 1 < nT) { CP_WAIT1(); } else { CP_WAIT0(); }
        __syncthreads();
        if (t + 2 < nT) load_tile((t + 2) % 3, (t + 2) * BKH);

        const __half* Ac = Asm + (t % 3) * A_STG;
        const __half* Bc = Bsm + (t % 3) * B_STG;
#pragma unroll
        for (int ks = 0; ks < 2; ks++) {
            const int kc = ks * 16;
            uint32_t a[4][4], b[8][2];
#pragma unroll
            for (int mi = 0; mi < 4; mi++) {
                int m0 = m_w + mi * 16;
                a[mi][0] = *reinterpret_cast<const uint32_t*>(Ac + (m0 + r4) * HSTR + kc + 2 * c4);
                a[mi][1] = *reinterpret_cast<const uint32_t*>(Ac + (m0 + r4 + 8) * HSTR + kc + 2 * c4);
                a[mi][2] = *reinterpret_cast<const uint32_t*>(Ac + (m0 + r4) * HSTR + kc + 2 * c4 + 8);
                a[mi][3] = *reinterpret_cast<const uint32_t*>(Ac + (m0 + r4 + 8) * HSTR + kc + 2 * c4 + 8);
            }
#pragma unroll
            for (int ni = 0; ni < 8; ni++) {
                int n0 = n_w + ni * 8;
                b[ni][0] = *reinterpret_cast<const uint32_t*>(Bc + (n0 + r4) * HSTR + kc + 2 * c4);
                b[ni][1] = *reinterpret_cast<const uint32_t*>(Bc + (n0 + r4) * HSTR + kc + 2 * c4 + 8);
            }
#pragma unroll
            for (int mi = 0; mi < 4; mi++)
#pragma unroll
                for (int ni = 0; ni < 8; ni++)
                    mma_f16(acc[mi][ni], a[mi], b[ni]);
        }
    }

    // epilogue
    const int row_base = by * BM + m_w;
    const int col_base = bx * BN + n_w;
#pragma unroll
    for (int mi = 0; mi < 4; mi++) {
#pragma unroll
        for (int ni = 0; ni < 8; ni++) {
            int c0 = col_base + ni * 8 + 2 * c4;
            float2 bb = *reinterpret_cast<const float2*>(bias + c0);
#pragma unroll
            for (int half = 0; half < 2; half++) {
                int r0 = row_base + mi * 16 + r4 + half * 8;
                float v0 = acc[mi][ni][half * 2]     + bb.x;
                float v1 = acc[mi][ni][half * 2 + 1] + bb.y;
                if (RELU) { v0 = fmaxf(v0, 0.f); v1 = fmaxf(v1, 0.f); }
                if (RES) {
                    float2 rr = *reinterpret_cast<const float2*>(resid + (size_t)r0 * N + c0);
                    v0 += rr.x; v1 += rr.y;
                }
                if (HALFOUT) {
                    *reinterpret_cast<__half2*>((__half*)Cout + (size_t)r0 * N + c0) =
                        __floats2half2_rn(v0, v1);
                } else {
                    float2 o2 = {v0, v1};
                    *reinterpret_cast<float2*>((float*)Cout + (size_t)r0 * N + c0) = o2;
                }
            }
        }
    }
}

// ---------------- launch ----------------
extern "C" void kernel_launch(void* const* d_in, const int* in_sizes, int n_in,
                              void* d_out, int out_size)
{
    (void)in_sizes; (void)n_in; (void)out_size;
    const float* x   = (const float*)d_in[0];
    const float* Wq  = (const float*)d_in[1];
    const float* Wk  = (const float*)d_in[2];
    const float* Wv  = (const float*)d_in[3];
    const float* Wo  = (const float*)d_in[4];
    const float* bo  = (const float*)d_in[5];
    const float* W1  = (const float*)d_in[6];
    const float* b1  = (const float*)d_in[7];
    const float* W2  = (const float*)d_in[8];
    const float* b2  = (const float*)d_in[9];
    const float* g1  = (const float*)d_in[10];
    const float* be1 = (const float*)d_in[11];
    const float* g2  = (const float*)d_in[12];
    const float* be2 = (const float*)d_in[13];
    float* out = (float*)d_out;

    float *nx, *x1;
    __half *qb, *kb, *vb, *ob, *nx2, *h1, *woT, *w1T, *w2T;
    cudaGetSymbolAddress((void**)&nx,  g_nx);
    cudaGetSymbolAddress((void**)&qb,  g_q);
    cudaGetSymbolAddress((void**)&kb,  g_k);
    cudaGetSymbolAddress((void**)&vb,  g_v);
    cudaGetSymbolAddress((void**)&ob,  g_o);
    cudaGetSymbolAddress((void**)&x1,  g_x1);
    cudaGetSymbolAddress((void**)&nx2, g_nx2);
    cudaGetSymbolAddress((void**)&h1,  g_h1);
    cudaGetSymbolAddress((void**)&woT, g_woT);
    cudaGetSymbolAddress((void**)&w1T, g_w1T);
    cudaGetSymbolAddress((void**)&w2T, g_w2T);

    cudaFuncSetAttribute(attn_kernel, cudaFuncAttributeMaxDynamicSharedMemorySize,
                         ATTN_SMEM_BYTES);
    cudaFuncSetAttribute(hgemm_kernel<0, 1, 0>, cudaFuncAttributeMaxDynamicSharedMemorySize,
                         GEMM_SMEM_BYTES);
    cudaFuncSetAttribute(hgemm_kernel<1, 0, 1>, cudaFuncAttributeMaxDynamicSharedMemorySize,
                         GEMM_SMEM_BYTES);

    // 0) transpose + fp16 weights: W[K][N] -> Wt[N][K]
    transpose_h_kernel<<<dim3(E_ / 32, E_ / 32), dim3(32, 8)>>>(Wo, woT, E_, E_);
    transpose_h_kernel<<<dim3(F_ / 32, E_ / 32), dim3(32, 8)>>>(W1, w1T, E_, F_);
    transpose_h_kernel<<<dim3(E_ / 32, F_ / 32), dim3(32, 8)>>>(W2, w2T, F_, E_);
    // 1) LN1 (f32 out)
    ln_kernel<0><<<TOK, 256>>>(x, g1, be1, nx);
    // 2) QKV projections (fp16 out)
    qkv_kernel<<<dim3(S_ / 64, H_, B_), 256>>>(nx, Wq, Wk, Wv, qb, kb, vb);
    // 3) causal flash attention (fp16 mma) -> o fp16
    attn_kernel<<<dim3(S_ / 64, H_, B_), 256, ATTN_SMEM_BYTES>>>(qb, kb, vb, ob);
    // 4) x1 = x + o @ Wo + bo   (f32 out)
    hgemm_kernel<0, 1, 0><<<dim3(E_ / BN, TOK / BM), 256, GEMM_SMEM_BYTES>>>(ob, woT, bo, x, x1, TOK, E_, E_);
    // 5) LN2 (fp16 out)
    ln_kernel<1><<<TOK, 256>>>(x1, g2, be2, nx2);
    // 6) h1 = relu(nx2 @ W1 + b1)  (fp16 out)
    hgemm_kernel<1, 0, 1><<<dim3(F_ / BN, TOK / BM), 256, GEMM_SMEM_BYTES>>>(nx2, w1T, b1, nullptr, h1, TOK, F_, E_);
    // 7) out = x1 + h1 @ W2 + b2   (f32 out)
    hgemm_kernel<0, 1, 0><<<dim3(E_ / BN, TOK / BM), 256, GEMM_SMEM_BYTES>>>(h1, w2T, b2, x1, out, TOK, E_, F_);
}

// round 10
// speedup vs baseline: 1.7953x; 1.1984x over previous
#include <cuda_runtime.h>
#include <cuda_fp16.h>
#include <math.h>
#include <stdint.h>

#define B_ 8
#define S_ 1024
#define E_ 1024
#define H_ 16
#define D_ 64
#define F_ 4096
#define TOK (B_ * S_)  // 8192

// ---------------- scratch (static device globals; no allocation) ----------------
__device__ __half g_nxh[(size_t)TOK * E_];
__device__ __half g_q  [(size_t)TOK * E_];
__device__ __half g_k  [(size_t)TOK * E_];
__device__ __half g_v  [(size_t)TOK * E_];
__device__ __half g_o  [(size_t)TOK * E_];
__device__ float  g_x1 [(size_t)TOK * E_];
__device__ __half g_nx2[(size_t)TOK * E_];
__device__ __half g_h1 [(size_t)TOK * F_];
__device__ __half g_woT[(size_t)E_ * E_];
__device__ __half g_w1T[(size_t)F_ * E_];
__device__ __half g_w2T[(size_t)E_ * F_];
__device__ __half g_wqT[(size_t)D_ * D_];
__device__ __half g_wkT[(size_t)D_ * D_];
__device__ __half g_wvT[(size_t)D_ * D_];

// ---------------- helpers ----------------
__device__ __forceinline__ void cp_async16(void* smem, const void* gmem) {
    uint32_t s = (uint32_t)__cvta_generic_to_shared(smem);
    asm volatile("cp.async.cg.shared.global [%0], [%1], 16;\n" :: "r"(s), "l"(gmem));
}
#define CP_COMMIT() asm volatile("cp.async.commit_group;\n" ::: "memory")
#define CP_WAIT0()  asm volatile("cp.async.wait_group 0;\n" ::: "memory")
#define CP_WAIT1()  asm volatile("cp.async.wait_group 1;\n" ::: "memory")

__device__ __forceinline__ void mma_f16(float c[4], const uint32_t a[4], const uint32_t b[2]) {
    asm volatile(
        "mma.sync.aligned.m16n8k16.row.col.f32.f16.f16.f32 "
        "{%0,%1,%2,%3}, {%4,%5,%6,%7}, {%8,%9}, {%0,%1,%2,%3};\n"
        : "+f"(c[0]), "+f"(c[1]), "+f"(c[2]), "+f"(c[3])
        : "r"(a[0]), "r"(a[1]), "r"(a[2]), "r"(a[3]), "r"(b[0]), "r"(b[1]));
}
__device__ __forceinline__ uint32_t packh2(float a, float b) {
    __half2 h = __floats2half2_rn(a, b);
    return *reinterpret_cast<uint32_t*>(&h);
}

// ---------------- weight transpose + fp16 round: in [K][N] f32 -> out [N][K] f16 ----------
__global__ __launch_bounds__(256) void transpose_h_kernel(const float* __restrict__ in,
                                                          __half* __restrict__ out,
                                                          int K, int N)
{
    __shared__ float tile[32][33];
    int bx = blockIdx.x;
    int by = blockIdx.y;
    int x = bx * 32 + threadIdx.x;
    int y0 = by * 32 + threadIdx.y;
#pragma unroll
    for (int j = 0; j < 32; j += 8)
        tile[threadIdx.y + j][threadIdx.x] = in[(size_t)(y0 + j) * N + x];
    __syncthreads();
    int xo = by * 32 + threadIdx.x;
    int yo = bx * 32 + threadIdx.y;
#pragma unroll
    for (int j = 0; j < 32; j += 8)
        out[(size_t)(yo + j) * K + xo] = __float2half_rn(tile[threadIdx.x][threadIdx.y + j]);
}

// ---------------- LayerNorm: one block per row of 1024 ----------------
template <int HALFOUT>
__global__ __launch_bounds__(256) void ln_kernel(const float* __restrict__ x,
                                                 const float* __restrict__ g,
                                                 const float* __restrict__ be,
                                                 void* __restrict__ out)
{
    int row = blockIdx.x;
    int tid = threadIdx.x;
    const float4* xr = reinterpret_cast<const float4*>(x + (size_t)row * E_);
    float4 a = xr[tid];
    float s  = a.x + a.y + a.z + a.w;
    float ss = a.x * a.x + a.y * a.y + a.z * a.z + a.w * a.w;
#pragma unroll
    for (int o = 16; o > 0; o >>= 1) {
        s  += __shfl_xor_sync(0xffffffffu, s,  o);
        ss += __shfl_xor_sync(0xffffffffu, ss, o);
    }
    __shared__ float sm[8], sm2[8];
    int w = tid >> 5, lane = tid & 31;
    if (lane == 0) { sm[w] = s; sm2[w] = ss; }
    __syncthreads();
    if (tid < 32) {
        s  = (tid < 8) ? sm[tid]  : 0.f;
        ss = (tid < 8) ? sm2[tid] : 0.f;
#pragma unroll
        for (int o = 4; o > 0; o >>= 1) {
            s  += __shfl_xor_sync(0xffffffffu, s,  o);
            ss += __shfl_xor_sync(0xffffffffu, ss, o);
        }
        if (tid == 0) { sm[0] = s; sm2[0] = ss; }
    }
    __syncthreads();
    float mean = sm[0] * (1.0f / E_);
    float var  = sm2[0] * (1.0f / E_) - mean * mean;
    float inv  = rsqrtf(var + 1e-5f);
    float4 gg = reinterpret_cast<const float4*>(g)[tid];
    float4 bb = reinterpret_cast<const float4*>(be)[tid];
    float4 o4;
    o4.x = (a.x - mean) * inv * gg.x + bb.x;
    o4.y = (a.y - mean) * inv * gg.y + bb.y;
    o4.z = (a.z - mean) * inv * gg.z + bb.z;
    o4.w = (a.w - mean) * inv * gg.w + bb.w;
    if (HALFOUT) {
        __half2* op = reinterpret_cast<__half2*>((__half*)out + (size_t)row * E_ + tid * 4);
        op[0] = __floats2half2_rn(o4.x, o4.y);
        op[1] = __floats2half2_rn(o4.z, o4.w);
    } else {
        reinterpret_cast<float4*>((float*)out + (size_t)row * E_)[tid] = o4;
    }
}

// ---------------- QKV projections via fp16 mma: per (64-token tile, head, batch) --------
#define AST 72   // halves; conflict-free for fragment pattern

__global__ __launch_bounds__(128) void qkv_kernel(const __half* __restrict__ nxh,
                                                  const __half* __restrict__ wqT,
                                                  const __half* __restrict__ wkT,
                                                  const __half* __restrict__ wvT,
                                                  __half* __restrict__ q,
                                                  __half* __restrict__ k,
                                                  __half* __restrict__ v)
{
    __shared__ __half Xh[64 * AST];
    __shared__ __half Wh[64 * AST];
    int st = blockIdx.x, h = blockIdx.y, b = blockIdx.z;
    int tid  = threadIdx.x;
    int lane = tid & 31, warp = tid >> 5;
    int m0 = warp * 16;
    int r4 = lane >> 2, c4 = lane & 3;

    // load X tile (64 tokens x head slice)
#pragma unroll
    for (int it = 0; it < 4; it++) {
        int idx = tid + it * 128;
        int r = idx >> 3, c8 = (idx & 7) * 8;
        uint4 raw = *reinterpret_cast<const uint4*>(
            nxh + ((size_t)(b * S_ + st * 64 + r)) * E_ + h * 64 + c8);
        *reinterpret_cast<uint4*>(Xh + r * AST + c8) = raw;
    }

    const __half* Wm[3] = {wqT, wkT, wvT};
    __half*       Om[3] = {q, k, v};
    size_t obase = ((size_t)(b * H_ + h) * S_ + st * 64) * D_;

#pragma unroll 1
    for (int m = 0; m < 3; m++) {
        __syncthreads();
#pragma unroll
        for (int it = 0; it < 4; it++) {
            int idx = tid + it * 128;
            int r = idx >> 3, c8 = (idx & 7) * 8;
            uint4 raw = *reinterpret_cast<const uint4*>(Wm[m] + r * 64 + c8);
            *reinterpret_cast<uint4*>(Wh + r * AST + c8) = raw;
        }
        __syncthreads();

        float acc[8][4] = {};
#pragma unroll
        for (int ks = 0; ks < 4; ks++) {
            int kc = ks * 16;
            uint32_t a[4];
            a[0] = *reinterpret_cast<const uint32_t*>(Xh + (m0 + r4) * AST + kc + 2 * c4);
            a[1] = *reinterpret_cast<const uint32_t*>(Xh + (m0 + r4 + 8) * AST + kc + 2 * c4);
            a[2] = *reinterpret_cast<const uint32_t*>(Xh + (m0 + r4) * AST + kc + 2 * c4 + 8);
            a[3] = *reinterpret_cast<const uint32_t*>(Xh + (m0 + r4 + 8) * AST + kc + 2 * c4 + 8);
#pragma unroll
            for (int ni = 0; ni < 8; ni++) {
                int n0 = ni * 8;
                uint32_t bf[2];
                bf[0] = *reinterpret_cast<const uint32_t*>(Wh + (n0 + r4) * AST + kc + 2 * c4);
                bf[1] = *reinterpret_cast<const uint32_t*>(Wh + (n0 + r4) * AST + kc + 2 * c4 + 8);
                mma_f16(acc[ni], a, bf);
            }
        }
        __half* dst = Om[m] + obase;
#pragma unroll
        for (int ni = 0; ni < 8; ni++) {
            int cc = ni * 8 + 2 * c4;
            *reinterpret_cast<uint32_t*>(dst + (m0 + r4) * D_ + cc)     = packh2(acc[ni][0], acc[ni][1]);
            *reinterpret_cast<uint32_t*>(dst + (m0 + r4 + 8) * D_ + cc) = packh2(acc[ni][2], acc[ni][3]);
        }
    }
}

// ---------------- Causal flash attention: register softmax, fp16 mma ----------------
// 4 warps / 128 threads; warp w owns rows 16w..16w+15 across all 64 cols.
__global__ __launch_bounds__(128) void attn_kernel(const __half* __restrict__ q,
                                                   const __half* __restrict__ k,
                                                   const __half* __restrict__ v,
                                                   __half* __restrict__ o)
{
    __shared__ __half Qh[64 * AST];
    __shared__ __half Kh[64 * AST];
    __shared__ __half Vt[64 * AST];   // d-major: Vt[d][s]

    int qt = blockIdx.x, h = blockIdx.y, b = blockIdx.z;
    int tid  = threadIdx.x;
    int lane = tid & 31, warp = tid >> 5;
    int m0 = warp * 16;
    int r4 = lane >> 2, c4 = lane & 3;
    size_t head_base = (size_t)(b * H_ + h) * S_ * D_;
    const __half2 hscale = __float2half2_rn(0.03125f);  // 1/32 exact

    // load Q (scaled)
#pragma unroll
    for (int it = 0; it < 4; it++) {
        int idx = tid + it * 128;
        int r = idx >> 3, c8 = (idx & 7) * 8;
        uint4 raw = *reinterpret_cast<const uint4*>(q + head_base + (size_t)(qt * 64 + r) * 64 + c8);
        __half2* hp = reinterpret_cast<__half2*>(&raw);
#pragma unroll
        for (int j = 0; j < 4; j++) hp[j] = __hmul2(hp[j], hscale);
        *reinterpret_cast<uint4*>(Qh + r * AST + c8) = raw;
    }

    float m_0 = -1e30f, m_1 = -1e30f, l_0 = 0.f, l_1 = 0.f;
    float acc_o[8][4] = {};

    for (int kt = 0; kt <= qt; kt++) {
        __syncthreads();
#pragma unroll
        for (int it = 0; it < 4; it++) {
            int idx = tid + it * 128;
            int r = idx >> 3, c8 = (idx & 7) * 8;
            uint4 kraw = *reinterpret_cast<const uint4*>(k + head_base + (size_t)(kt * 64 + r) * 64 + c8);
            *reinterpret_cast<uint4*>(Kh + r * AST + c8) = kraw;
            uint4 vraw = *reinterpret_cast<const uint4*>(v + head_base + (size_t)(kt * 64 + r) * 64 + c8);
            const __half* vh = reinterpret_cast<const __half*>(&vraw);
#pragma unroll
            for (int j = 0; j < 8; j++) Vt[(c8 + j) * AST + r] = vh[j];
        }
        __syncthreads();

        // ---- S = Q @ K^T : warp computes 16x64 in registers ----
        float s[8][4] = {};
#pragma unroll
        for (int ks = 0; ks < 4; ks++) {
            int kc = ks * 16;
            uint32_t a[4];
            a[0] = *reinterpret_cast<const uint32_t*>(Qh + (m0 + r4) * AST + kc + 2 * c4);
            a[1] = *reinterpret_cast<const uint32_t*>(Qh + (m0 + r4 + 8) * AST + kc + 2 * c4);
            a[2] = *reinterpret_cast<const uint32_t*>(Qh + (m0 + r4) * AST + kc + 2 * c4 + 8);
            a[3] = *reinterpret_cast<const uint32_t*>(Qh + (m0 + r4 + 8) * AST + kc + 2 * c4 + 8);
#pragma unroll
            for (int ni = 0; ni < 8; ni++) {
                int n0 = ni * 8;
                uint32_t bf[2];
                bf[0] = *reinterpret_cast<const uint32_t*>(Kh + (n0 + r4) * AST + kc + 2 * c4);
                bf[1] = *reinterpret_cast<const uint32_t*>(Kh + (n0 + r4) * AST + kc + 2 * c4 + 8);
                mma_f16(s[ni], a, bf);
            }
        }

        // causal mask on diagonal tile
        if (kt == qt) {
            int row0 = m0 + r4, row1 = m0 + r4 + 8;
#pragma unroll
            for (int ni = 0; ni < 8; ni++) {
                int col = ni * 8 + 2 * c4;
                if (col > row0)     s[ni][0] = -1e30f;
                if (col + 1 > row0) s[ni][1] = -1e30f;
                if (col > row1)     s[ni][2] = -1e30f;
                if (col + 1 > row1) s[ni][3] = -1e30f;
            }
        }

        // ---- register softmax ----
        float mx0 = -1e30f, mx1 = -1e30f;
#pragma unroll
        for (int ni = 0; ni < 8; ni++) {
            mx0 = fmaxf(mx0, fmaxf(s[ni][0], s[ni][1]));
            mx1 = fmaxf(mx1, fmaxf(s[ni][2], s[ni][3]));
        }
        mx0 = fmaxf(mx0, __shfl_xor_sync(0xffffffffu, mx0, 1));
        mx0 = fmaxf(mx0, __shfl_xor_sync(0xffffffffu, mx0, 2));
        mx1 = fmaxf(mx1, __shfl_xor_sync(0xffffffffu, mx1, 1));
        mx1 = fmaxf(mx1, __shfl_xor_sync(0xffffffffu, mx1, 2));

        float mn0 = fmaxf(m_0, mx0), mn1 = fmaxf(m_1, mx1);
        float corr0 = expf(m_0 - mn0), corr1 = expf(m_1 - mn1);
        float rs0 = 0.f, rs1 = 0.f;
#pragma unroll
        for (int ni = 0; ni < 8; ni++) {
            s[ni][0] = expf(s[ni][0] - mn0);
            s[ni][1] = expf(s[ni][1] - mn0);
            s[ni][2] = expf(s[ni][2] - mn1);
            s[ni][3] = expf(s[ni][3] - mn1);
            rs0 += s[ni][0] + s[ni][1];
            rs1 += s[ni][2] + s[ni][3];
        }
        rs0 += __shfl_xor_sync(0xffffffffu, rs0, 1);
        rs0 += __shfl_xor_sync(0xffffffffu, rs0, 2);
        rs1 += __shfl_xor_sync(0xffffffffu, rs1, 1);
        rs1 += __shfl_xor_sync(0xffffffffu, rs1, 2);
        l_0 = l_0 * corr0 + rs0;  m_0 = mn0;
        l_1 = l_1 * corr1 + rs1;  m_1 = mn1;

        // pack P into A-fragments (S C-frag layout == P A-frag layout)
        uint32_t pa[4][4];
#pragma unroll
        for (int kk = 0; kk < 4; kk++) {
            pa[kk][0] = packh2(s[2 * kk][0],     s[2 * kk][1]);
            pa[kk][1] = packh2(s[2 * kk][2],     s[2 * kk][3]);
            pa[kk][2] = packh2(s[2 * kk + 1][0], s[2 * kk + 1][1]);
            pa[kk][3] = packh2(s[2 * kk + 1][2], s[2 * kk + 1][3]);
        }

        // O = O*corr + P @ V
#pragma unroll
        for (int ni = 0; ni < 8; ni++) {
            acc_o[ni][0] *= corr0; acc_o[ni][1] *= corr0;
            acc_o[ni][2] *= corr1; acc_o[ni][3] *= corr1;
        }
#pragma unroll
        for (int kk = 0; kk < 4; kk++) {
            int kc = kk * 16;
#pragma unroll
            for (int ni = 0; ni < 8; ni++) {
                int n0 = ni * 8;  // d-dim
                uint32_t bf[2];
                bf[0] = *reinterpret_cast<const uint32_t*>(Vt + (n0 + r4) * AST + kc + 2 * c4);
                bf[1] = *reinterpret_cast<const uint32_t*>(Vt + (n0 + r4) * AST + kc + 2 * c4 + 8);
                mma_f16(acc_o[ni], pa[kk], bf);
            }
        }
    }

    // epilogue: normalize, fp16, token-major [B,S,H,D]
    float inv0 = 1.0f / l_0;
    float inv1 = 1.0f / l_1;
    __half* ob = o + ((size_t)(b * S_ + qt * 64)) * E_ + h * 64;
#pragma unroll
    for (int ni = 0; ni < 8; ni++) {
        int cc = ni * 8 + 2 * c4;
        *reinterpret_cast<uint32_t*>(ob + (size_t)(m0 + r4) * E_ + cc) =
            packh2(acc_o[ni][0] * inv0, acc_o[ni][1] * inv0);
        *reinterpret_cast<uint32_t*>(ob + (size_t)(m0 + r4 + 8) * E_ + cc) =
            packh2(acc_o[ni][2] * inv1, acc_o[ni][3] * inv1);
    }
}

// ---------------- FP16 GEMM: 128x256x32 tiles, warp 64x64, 3-stage cp.async ------------
#define BM 128
#define BN 256
#define BKH 32
#define HSTR 40
#define A_STG (BM * HSTR)
#define B_STG (BN * HSTR)
#define GEMM_SMEM_BYTES (3 * (A_STG + B_STG) * 2)   // 92160

template <int RELU, int RES, int HALFOUT>
__global__ __launch_bounds__(256) void hgemm_kernel(const __half* __restrict__ A,
                                                    const __half* __restrict__ Bt,
                                                    const float* __restrict__ bias,
                                                    const float* __restrict__ resid,
                                                    void* __restrict__ Cout,
                                                    int M, int N, int K)
{
    extern __shared__ __half shh[];
    __half* Asm = shh;
    __half* Bsm = shh + 3 * A_STG;

    const int tid  = threadIdx.x;
    const int lane = tid & 31;
    const int warp = tid >> 5;
    const int wm = warp >> 2;
    const int wn = warp & 3;
    const int m_w = wm * 64;
    const int n_w = wn * 64;
    const int r4 = lane >> 2;
    const int c4 = lane & 3;
    const int bx = blockIdx.x, by = blockIdx.y;

    const __half* Ab = A  + (size_t)by * BM * K;
    const __half* Bb = Bt + (size_t)bx * BN * K;

    auto load_tile = [&](int buf, int k0) {
        __half* Ad = Asm + buf * A_STG;
        __half* Bd = Bsm + buf * B_STG;
#pragma unroll
        for (int i = 0; i < 2; i++) {
            int idx = tid + i * 256;
            int row = idx >> 2, kq = (idx & 3) * 8;
            cp_async16(Ad + row * HSTR + kq, Ab + (size_t)row * K + k0 + kq);
        }
#pragma unroll
        for (int i = 0; i < 4; i++) {
            int idx = tid + i * 256;
            int row = idx >> 2, kq = (idx & 3) * 8;
            cp_async16(Bd + row * HSTR + kq, Bb + (size_t)row * K + k0 + kq);
        }
        CP_COMMIT();
    };

    float acc[4][8][4] = {};

    const int nT = K / BKH;
    load_tile(0, 0);
    load_tile(1, BKH);

#pragma unroll 1
    for (int t = 0; t < nT; t++) {
        if (t + 1 < nT) { CP_WAIT1(); } else { CP_WAIT0(); }
        __syncthreads();
        if (t + 2 < nT) load_tile((t + 2) % 3, (t + 2) * BKH);

        const __half* Ac = Asm + (t % 3) * A_STG;
        const __half* Bc = Bsm + (t % 3) * B_STG;
#pragma unroll
        for (int ks = 0; ks < 2; ks++) {
            const int kc = ks * 16;
            uint32_t a[4][4], b[8][2];
#pragma unroll
            for (int mi = 0; mi < 4; mi++) {
                int m0 = m_w + mi * 16;
                a[mi][0] = *reinterpret_cast<const uint32_t*>(Ac + (m0 + r4) * HSTR + kc + 2 * c4);
                a[mi][1] = *reinterpret_cast<const uint32_t*>(Ac + (m0 + r4 + 8) * HSTR + kc + 2 * c4);
                a[mi][2] = *reinterpret_cast<const uint32_t*>(Ac + (m0 + r4) * HSTR + kc + 2 * c4 + 8);
                a[mi][3] = *reinterpret_cast<const uint32_t*>(Ac + (m0 + r4 + 8) * HSTR + kc + 2 * c4 + 8);
            }
#pragma unroll
            for (int ni = 0; ni < 8; ni++) {
                int n0 = n_w + ni * 8;
                b[ni][0] = *reinterpret_cast<const uint32_t*>(Bc + (n0 + r4) * HSTR + kc + 2 * c4);
                b[ni][1] = *reinterpret_cast<const uint32_t*>(Bc + (n0 + r4) * HSTR + kc + 2 * c4 + 8);
            }
#pragma unroll
            for (int mi = 0; mi < 4; mi++)
#pragma unroll
                for (int ni = 0; ni < 8; ni++)
                    mma_f16(acc[mi][ni], a[mi], b[ni]);
        }
    }

    const int row_base = by * BM + m_w;
    const int col_base = bx * BN + n_w;
#pragma unroll
    for (int mi = 0; mi < 4; mi++) {
#pragma unroll
        for (int ni = 0; ni < 8; ni++) {
            int c0 = col_base + ni * 8 + 2 * c4;
            float2 bb = *reinterpret_cast<const float2*>(bias + c0);
#pragma unroll
            for (int half = 0; half < 2; half++) {
                int r0 = row_base + mi * 16 + r4 + half * 8;
                float v0 = acc[mi][ni][half * 2]     + bb.x;
                float v1 = acc[mi][ni][half * 2 + 1] + bb.y;
                if (RELU) { v0 = fmaxf(v0, 0.f); v1 = fmaxf(v1, 0.f); }
                if (RES) {
                    float2 rr = *reinterpret_cast<const float2*>(resid + (size_t)r0 * N + c0);
                    v0 += rr.x; v1 += rr.y;
                }
                if (HALFOUT) {
                    *reinterpret_cast<__half2*>((__half*)Cout + (size_t)r0 * N + c0) =
                        __floats2half2_rn(v0, v1);
                } else {
                    float2 o2 = {v0, v1};
                    *reinterpret_cast<float2*>((float*)Cout + (size_t)r0 * N + c0) = o2;
                }
            }
        }
    }
}

// ---------------- launch ----------------
extern "C" void kernel_launch(void* const* d_in, const int* in_sizes, int n_in,
                              void* d_out, int out_size)
{
    (void)in_sizes; (void)n_in; (void)out_size;
    const float* x   = (const float*)d_in[0];
    const float* Wq  = (const float*)d_in[1];
    const float* Wk  = (const float*)d_in[2];
    const float* Wv  = (const float*)d_in[3];
    const float* Wo  = (const float*)d_in[4];
    const float* bo  = (const float*)d_in[5];
    const float* W1  = (const float*)d_in[6];
    const float* b1  = (const float*)d_in[7];
    const float* W2  = (const float*)d_in[8];
    const float* b2  = (const float*)d_in[9];
    const float* g1  = (const float*)d_in[10];
    const float* be1 = (const float*)d_in[11];
    const float* g2  = (const float*)d_in[12];
    const float* be2 = (const float*)d_in[13];
    float* out = (float*)d_out;

    float *x1;
    __half *nxh, *qb, *kb, *vb, *ob, *nx2, *h1, *woT, *w1T, *w2T, *wqT, *wkT, *wvT;
    cudaGetSymbolAddress((void**)&nxh, g_nxh);
    cudaGetSymbolAddress((void**)&qb,  g_q);
    cudaGetSymbolAddress((void**)&kb,  g_k);
    cudaGetSymbolAddress((void**)&vb,  g_v);
    cudaGetSymbolAddress((void**)&ob,  g_o);
    cudaGetSymbolAddress((void**)&x1,  g_x1);
    cudaGetSymbolAddress((void**)&nx2, g_nx2);
    cudaGetSymbolAddress((void**)&h1,  g_h1);
    cudaGetSymbolAddress((void**)&woT, g_woT);
    cudaGetSymbolAddress((void**)&w1T, g_w1T);
    cudaGetSymbolAddress((void**)&w2T, g_w2T);
    cudaGetSymbolAddress((void**)&wqT, g_wqT);
    cudaGetSymbolAddress((void**)&wkT, g_wkT);
    cudaGetSymbolAddress((void**)&wvT, g_wvT);

    cudaFuncSetAttribute(hgemm_kernel<0, 1, 0>, cudaFuncAttributeMaxDynamicSharedMemorySize,
                         GEMM_SMEM_BYTES);
    cudaFuncSetAttribute(hgemm_kernel<1, 0, 1>, cudaFuncAttributeMaxDynamicSharedMemorySize,
                         GEMM_SMEM_BYTES);

    // 0) transpose + fp16 weights
    transpose_h_kernel<<<dim3(2, 2), dim3(32, 8)>>>(Wq, wqT, D_, D_);
    transpose_h_kernel<<<dim3(2, 2), dim3(32, 8)>>>(Wk, wkT, D_, D_);
    transpose_h_kernel<<<dim3(2, 2), dim3(32, 8)>>>(Wv, wvT, D_, D_);
    transpose_h_kernel<<<dim3(E_ / 32, E_ / 32), dim3(32, 8)>>>(Wo, woT, E_, E_);
    transpose_h_kernel<<<dim3(F_ / 32, E_ / 32), dim3(32, 8)>>>(W1, w1T, E_, F_);
    transpose_h_kernel<<<dim3(E_ / 32, F_ / 32), dim3(32, 8)>>>(W2, w2T, F_, E_);
    // 1) LN1 (fp16 out)
    ln_kernel<1><<<TOK, 256>>>(x, g1, be1, nxh);
    // 2) QKV projections (fp16 mma)
    qkv_kernel<<<dim3(S_ / 64, H_, B_), 128>>>(nxh, wqT, wkT, wvT, qb, kb, vb);
    // 3) causal flash attention (register softmax) -> o fp16
    attn_kernel<<<dim3(S_ / 64, H_, B_), 128>>>(qb, kb, vb, ob);
    // 4) x1 = x + o @ Wo + bo   (f32 out)
    hgemm_kernel<0, 1, 0><<<dim3(E_ / BN, TOK / BM), 256, GEMM_SMEM_BYTES>>>(ob, woT, bo, x, x1, TOK, E_, E_);
    // 5) LN2 (fp16 out)
    ln_kernel<1><<<TOK, 256>>>(x1, g2, be2, nx2);
    // 6) h1 = relu(nx2 @ W1 + b1)  (fp16 out)
    hgemm_kernel<1, 0, 1><<<dim3(F_ / BN, TOK / BM), 256, GEMM_SMEM_BYTES>>>(nx2, w1T, b1, nullptr, h1, TOK, F_, E_);
    // 7) out = x1 + h1 @ W2 + b2   (f32 out)
    hgemm_kernel<0, 1, 0><<<dim3(E_ / BN, TOK / BM), 256, GEMM_SMEM_BYTES>>>(h1, w2T, b2, x1, out, TOK, E_, F_);
}

// round 11
// speedup vs baseline: 1.8053x; 1.0056x over previous
#include <cuda_runtime.h>
#include <cuda_fp16.h>
#include <math.h>
#include <stdint.h>

#define B_ 8
#define S_ 1024
#define E_ 1024
#define H_ 16
#define D_ 64
#define F_ 4096
#define TOK (B_ * S_)  // 8192

// ---------------- scratch (static device globals; no allocation) ----------------
__device__ __half g_nxh[(size_t)TOK * E_];
__device__ __half g_q  [(size_t)TOK * E_];
__device__ __half g_k  [(size_t)TOK * E_];
__device__ __half g_v  [(size_t)TOK * E_];
__device__ __half g_o  [(size_t)TOK * E_];
__device__ float  g_x1 [(size_t)TOK * E_];
__device__ __half g_nx2[(size_t)TOK * E_];
__device__ __half g_h1 [(size_t)TOK * F_];
__device__ __half g_woT[(size_t)E_ * E_];
__device__ __half g_w1T[(size_t)F_ * E_];
__device__ __half g_w2T[(size_t)E_ * F_];
__device__ __half g_wqT[(size_t)D_ * D_];
__device__ __half g_wkT[(size_t)D_ * D_];
__device__ __half g_wvT[(size_t)D_ * D_];

// ---------------- helpers ----------------
__device__ __forceinline__ void cp_async16(void* smem, const void* gmem) {
    uint32_t s = (uint32_t)__cvta_generic_to_shared(smem);
    asm volatile("cp.async.cg.shared.global [%0], [%1], 16;\n" :: "r"(s), "l"(gmem));
}
#define CP_COMMIT() asm volatile("cp.async.commit_group;\n" ::: "memory")
#define CP_WAIT0()  asm volatile("cp.async.wait_group 0;\n" ::: "memory")
#define CP_WAIT1()  asm volatile("cp.async.wait_group 1;\n" ::: "memory")

__device__ __forceinline__ void mma_f16(float c[4], const uint32_t a[4], const uint32_t b[2]) {
    asm volatile(
        "mma.sync.aligned.m16n8k16.row.col.f32.f16.f16.f32 "
        "{%0,%1,%2,%3}, {%4,%5,%6,%7}, {%8,%9}, {%0,%1,%2,%3};\n"
        : "+f"(c[0]), "+f"(c[1]), "+f"(c[2]), "+f"(c[3])
        : "r"(a[0]), "r"(a[1]), "r"(a[2]), "r"(a[3]), "r"(b[0]), "r"(b[1]));
}
__device__ __forceinline__ uint32_t packh2(float a, float b) {
    __half2 h = __floats2half2_rn(a, b);
    return *reinterpret_cast<uint32_t*>(&h);
}

// ---------------- weight transpose + fp16 round: in [K][N] f32 -> out [N][K] f16 ----------
__global__ __launch_bounds__(256) void transpose_h_kernel(const float* __restrict__ in,
                                                          __half* __restrict__ out,
                                                          int K, int N)
{
    __shared__ float tile[32][33];
    int bx = blockIdx.x;
    int by = blockIdx.y;
    int x = bx * 32 + threadIdx.x;
    int y0 = by * 32 + threadIdx.y;
#pragma unroll
    for (int j = 0; j < 32; j += 8)
        tile[threadIdx.y + j][threadIdx.x] = in[(size_t)(y0 + j) * N + x];
    __syncthreads();
    int xo = by * 32 + threadIdx.x;
    int yo = bx * 32 + threadIdx.y;
#pragma unroll
    for (int j = 0; j < 32; j += 8)
        out[(size_t)(yo + j) * K + xo] = __float2half_rn(tile[threadIdx.x][threadIdx.y + j]);
}

// ---------------- LayerNorm: one block per row of 1024 ----------------
template <int HALFOUT>
__global__ __launch_bounds__(256) void ln_kernel(const float* __restrict__ x,
                                                 const float* __restrict__ g,
                                                 const float* __restrict__ be,
                                                 void* __restrict__ out)
{
    int row = blockIdx.x;
    int tid = threadIdx.x;
    const float4* xr = reinterpret_cast<const float4*>(x + (size_t)row * E_);
    float4 a = xr[tid];
    float s  = a.x + a.y + a.z + a.w;
    float ss = a.x * a.x + a.y * a.y + a.z * a.z + a.w * a.w;
#pragma unroll
    for (int o = 16; o > 0; o >>= 1) {
        s  += __shfl_xor_sync(0xffffffffu, s,  o);
        ss += __shfl_xor_sync(0xffffffffu, ss, o);
    }
    __shared__ float sm[8], sm2[8];
    int w = tid >> 5, lane = tid & 31;
    if (lane == 0) { sm[w] = s; sm2[w] = ss; }
    __syncthreads();
    if (tid < 32) {
        s  = (tid < 8) ? sm[tid]  : 0.f;
        ss = (tid < 8) ? sm2[tid] : 0.f;
#pragma unroll
        for (int o = 4; o > 0; o >>= 1) {
            s  += __shfl_xor_sync(0xffffffffu, s,  o);
            ss += __shfl_xor_sync(0xffffffffu, ss, o);
        }
        if (tid == 0) { sm[0] = s; sm2[0] = ss; }
    }
    __syncthreads();
    float mean = sm[0] * (1.0f / E_);
    float var  = sm2[0] * (1.0f / E_) - mean * mean;
    float inv  = rsqrtf(var + 1e-5f);
    float4 gg = reinterpret_cast<const float4*>(g)[tid];
    float4 bb = reinterpret_cast<const float4*>(be)[tid];
    float4 o4;
    o4.x = (a.x - mean) * inv * gg.x + bb.x;
    o4.y = (a.y - mean) * inv * gg.y + bb.y;
    o4.z = (a.z - mean) * inv * gg.z + bb.z;
    o4.w = (a.w - mean) * inv * gg.w + bb.w;
    if (HALFOUT) {
        __half2* op = reinterpret_cast<__half2*>((__half*)out + (size_t)row * E_ + tid * 4);
        op[0] = __floats2half2_rn(o4.x, o4.y);
        op[1] = __floats2half2_rn(o4.z, o4.w);
    } else {
        reinterpret_cast<float4*>((float*)out + (size_t)row * E_)[tid] = o4;
    }
}

// ---------------- QKV projections via fp16 mma: per (64-token tile, head, batch) --------
#define AST 72   // halves; conflict-free for fragment pattern

__global__ __launch_bounds__(128) void qkv_kernel(const __half* __restrict__ nxh,
                                                  const __half* __restrict__ wqT,
                                                  const __half* __restrict__ wkT,
                                                  const __half* __restrict__ wvT,
                                                  __half* __restrict__ q,
                                                  __half* __restrict__ k,
                                                  __half* __restrict__ v)
{
    __shared__ __half Xh[64 * AST];
    __shared__ __half Wh[64 * AST];
    int st = blockIdx.x, h = blockIdx.y, b = blockIdx.z;
    int tid  = threadIdx.x;
    int lane = tid & 31, warp = tid >> 5;
    int m0 = warp * 16;
    int r4 = lane >> 2, c4 = lane & 3;

#pragma unroll
    for (int it = 0; it < 4; it++) {
        int idx = tid + it * 128;
        int r = idx >> 3, c8 = (idx & 7) * 8;
        uint4 raw = *reinterpret_cast<const uint4*>(
            nxh + ((size_t)(b * S_ + st * 64 + r)) * E_ + h * 64 + c8);
        *reinterpret_cast<uint4*>(Xh + r * AST + c8) = raw;
    }

    const __half* Wm[3] = {wqT, wkT, wvT};
    __half*       Om[3] = {q, k, v};
    size_t obase = ((size_t)(b * H_ + h) * S_ + st * 64) * D_;

#pragma unroll 1
    for (int m = 0; m < 3; m++) {
        __syncthreads();
#pragma unroll
        for (int it = 0; it < 4; it++) {
            int idx = tid + it * 128;
            int r = idx >> 3, c8 = (idx & 7) * 8;
            uint4 raw = *reinterpret_cast<const uint4*>(Wm[m] + r * 64 + c8);
            *reinterpret_cast<uint4*>(Wh + r * AST + c8) = raw;
        }
        __syncthreads();

        float acc[8][4] = {};
#pragma unroll
        for (int ks = 0; ks < 4; ks++) {
            int kc = ks * 16;
            uint32_t a[4];
            a[0] = *reinterpret_cast<const uint32_t*>(Xh + (m0 + r4) * AST + kc + 2 * c4);
            a[1] = *reinterpret_cast<const uint32_t*>(Xh + (m0 + r4 + 8) * AST + kc + 2 * c4);
            a[2] = *reinterpret_cast<const uint32_t*>(Xh + (m0 + r4) * AST + kc + 2 * c4 + 8);
            a[3] = *reinterpret_cast<const uint32_t*>(Xh + (m0 + r4 + 8) * AST + kc + 2 * c4 + 8);
#pragma unroll
            for (int ni = 0; ni < 8; ni++) {
                int n0 = ni * 8;
                uint32_t bf[2];
                bf[0] = *reinterpret_cast<const uint32_t*>(Wh + (n0 + r4) * AST + kc + 2 * c4);
                bf[1] = *reinterpret_cast<const uint32_t*>(Wh + (n0 + r4) * AST + kc + 2 * c4 + 8);
                mma_f16(acc[ni], a, bf);
            }
        }
        __half* dst = Om[m] + obase;
#pragma unroll
        for (int ni = 0; ni < 8; ni++) {
            int cc = ni * 8 + 2 * c4;
            *reinterpret_cast<uint32_t*>(dst + (m0 + r4) * D_ + cc)     = packh2(acc[ni][0], acc[ni][1]);
            *reinterpret_cast<uint32_t*>(dst + (m0 + r4 + 8) * D_ + cc) = packh2(acc[ni][2], acc[ni][3]);
        }
    }
}

// ---------------- Causal flash attention: register softmax, fp16 mma ----------------
__global__ __launch_bounds__(128) void attn_kernel(const __half* __restrict__ q,
                                                   const __half* __restrict__ k,
                                                   const __half* __restrict__ v,
                                                   __half* __restrict__ o)
{
    __shared__ __half Qh[64 * AST];
    __shared__ __half Kh[64 * AST];
    __shared__ __half Vt[64 * AST];   // d-major: Vt[d][s]

    int qt = blockIdx.x, h = blockIdx.y, b = blockIdx.z;
    int tid  = threadIdx.x;
    int lane = tid & 31, warp = tid >> 5;
    int m0 = warp * 16;
    int r4 = lane >> 2, c4 = lane & 3;
    size_t head_base = (size_t)(b * H_ + h) * S_ * D_;
    const __half2 hscale = __float2half2_rn(0.03125f);  // 1/32 exact

#pragma unroll
    for (int it = 0; it < 4; it++) {
        int idx = tid + it * 128;
        int r = idx >> 3, c8 = (idx & 7) * 8;
        uint4 raw = *reinterpret_cast<const uint4*>(q + head_base + (size_t)(qt * 64 + r) * 64 + c8);
        __half2* hp = reinterpret_cast<__half2*>(&raw);
#pragma unroll
        for (int j = 0; j < 4; j++) hp[j] = __hmul2(hp[j], hscale);
        *reinterpret_cast<uint4*>(Qh + r * AST + c8) = raw;
    }

    float m_0 = -1e30f, m_1 = -1e30f, l_0 = 0.f, l_1 = 0.f;
    float acc_o[8][4] = {};

    for (int kt = 0; kt <= qt; kt++) {
        __syncthreads();
#pragma unroll
        for (int it = 0; it < 4; it++) {
            int idx = tid + it * 128;
            int r = idx >> 3, c8 = (idx & 7) * 8;
            uint4 kraw = *reinterpret_cast<const uint4*>(k + head_base + (size_t)(kt * 64 + r) * 64 + c8);
            *reinterpret_cast<uint4*>(Kh + r * AST + c8) = kraw;
            uint4 vraw = *reinterpret_cast<const uint4*>(v + head_base + (size_t)(kt * 64 + r) * 64 + c8);
            const __half* vh = reinterpret_cast<const __half*>(&vraw);
#pragma unroll
            for (int j = 0; j < 8; j++) Vt[(c8 + j) * AST + r] = vh[j];
        }
        __syncthreads();

        float s[8][4] = {};
#pragma unroll
        for (int ks = 0; ks < 4; ks++) {
            int kc = ks * 16;
            uint32_t a[4];
            a[0] = *reinterpret_cast<const uint32_t*>(Qh + (m0 + r4) * AST + kc + 2 * c4);
            a[1] = *reinterpret_cast<const uint32_t*>(Qh + (m0 + r4 + 8) * AST + kc + 2 * c4);
            a[2] = *reinterpret_cast<const uint32_t*>(Qh + (m0 + r4) * AST + kc + 2 * c4 + 8);
            a[3] = *reinterpret_cast<const uint32_t*>(Qh + (m0 + r4 + 8) * AST + kc + 2 * c4 + 8);
#pragma unroll
            for (int ni = 0; ni < 8; ni++) {
                int n0 = ni * 8;
                uint32_t bf[2];
                bf[0] = *reinterpret_cast<const uint32_t*>(Kh + (n0 + r4) * AST + kc + 2 * c4);
                bf[1] = *reinterpret_cast<const uint32_t*>(Kh + (n0 + r4) * AST + kc + 2 * c4 + 8);
                mma_f16(s[ni], a, bf);
            }
        }

        if (kt == qt) {
            int row0 = m0 + r4, row1 = m0 + r4 + 8;
#pragma unroll
            for (int ni = 0; ni < 8; ni++) {
                int col = ni * 8 + 2 * c4;
                if (col > row0)     s[ni][0] = -1e30f;
                if (col + 1 > row0) s[ni][1] = -1e30f;
                if (col > row1)     s[ni][2] = -1e30f;
                if (col + 1 > row1) s[ni][3] = -1e30f;
            }
        }

        float mx0 = -1e30f, mx1 = -1e30f;
#pragma unroll
        for (int ni = 0; ni < 8; ni++) {
            mx0 = fmaxf(mx0, fmaxf(s[ni][0], s[ni][1]));
            mx1 = fmaxf(mx1, fmaxf(s[ni][2], s[ni][3]));
        }
        mx0 = fmaxf(mx0, __shfl_xor_sync(0xffffffffu, mx0, 1));
        mx0 = fmaxf(mx0, __shfl_xor_sync(0xffffffffu, mx0, 2));
        mx1 = fmaxf(mx1, __shfl_xor_sync(0xffffffffu, mx1, 1));
        mx1 = fmaxf(mx1, __shfl_xor_sync(0xffffffffu, mx1, 2));

        float mn0 = fmaxf(m_0, mx0), mn1 = fmaxf(m_1, mx1);
        float corr0 = expf(m_0 - mn0), corr1 = expf(m_1 - mn1);
        float rs0 = 0.f, rs1 = 0.f;
#pragma unroll
        for (int ni = 0; ni < 8; ni++) {
            s[ni][0] = expf(s[ni][0] - mn0);
            s[ni][1] = expf(s[ni][1] - mn0);
            s[ni][2] = expf(s[ni][2] - mn1);
            s[ni][3] = expf(s[ni][3] - mn1);
            rs0 += s[ni][0] + s[ni][1];
            rs1 += s[ni][2] + s[ni][3];
        }
        rs0 += __shfl_xor_sync(0xffffffffu, rs0, 1);
        rs0 += __shfl_xor_sync(0xffffffffu, rs0, 2);
        rs1 += __shfl_xor_sync(0xffffffffu, rs1, 1);
        rs1 += __shfl_xor_sync(0xffffffffu, rs1, 2);
        l_0 = l_0 * corr0 + rs0;  m_0 = mn0;
        l_1 = l_1 * corr1 + rs1;  m_1 = mn1;

        uint32_t pa[4][4];
#pragma unroll
        for (int kk = 0; kk < 4; kk++) {
            pa[kk][0] = packh2(s[2 * kk][0],     s[2 * kk][1]);
            pa[kk][1] = packh2(s[2 * kk][2],     s[2 * kk][3]);
            pa[kk][2] = packh2(s[2 * kk + 1][0], s[2 * kk + 1][1]);
            pa[kk][3] = packh2(s[2 * kk + 1][2], s[2 * kk + 1][3]);
        }

#pragma unroll
        for (int ni = 0; ni < 8; ni++) {
            acc_o[ni][0] *= corr0; acc_o[ni][1] *= corr0;
            acc_o[ni][2] *= corr1; acc_o[ni][3] *= corr1;
        }
#pragma unroll
        for (int kk = 0; kk < 4; kk++) {
            int kc = kk * 16;
#pragma unroll
            for (int ni = 0; ni < 8; ni++) {
                int n0 = ni * 8;
                uint32_t bf[2];
                bf[0] = *reinterpret_cast<const uint32_t*>(Vt + (n0 + r4) * AST + kc + 2 * c4);
                bf[1] = *reinterpret_cast<const uint32_t*>(Vt + (n0 + r4) * AST + kc + 2 * c4 + 8);
                mma_f16(acc_o[ni], pa[kk], bf);
            }
        }
    }

    float inv0 = 1.0f / l_0;
    float inv1 = 1.0f / l_1;
    __half* ob = o + ((size_t)(b * S_ + qt * 64)) * E_ + h * 64;
#pragma unroll
    for (int ni = 0; ni < 8; ni++) {
        int cc = ni * 8 + 2 * c4;
        *reinterpret_cast<uint32_t*>(ob + (size_t)(m0 + r4) * E_ + cc) =
            packh2(acc_o[ni][0] * inv0, acc_o[ni][1] * inv0);
        *reinterpret_cast<uint32_t*>(ob + (size_t)(m0 + r4 + 8) * E_ + cc) =
            packh2(acc_o[ni][2] * inv1, acc_o[ni][3] * inv1);
    }
}

// ---------------- FP16 GEMM: 128x256x32 tiles, warp 64x64, 3-stage cp.async ------------
#define BM 128
#define BN 256
#define BKH 32
#define HSTR 40
#define A_STG (BM * HSTR)
#define B_STG (BN * HSTR)
#define GEMM_SMEM_BYTES (3 * (A_STG + B_STG) * 2)   // 92160

template <int RELU, int RES, int HALFOUT>
__global__ __launch_bounds__(256) void hgemm_kernel(const __half* __restrict__ A,
                                                    const __half* __restrict__ Bt,
                                                    const float* __restrict__ bias,
                                                    const float* __restrict__ resid,
                                                    void* __restrict__ Cout,
                                                    int M, int N, int K)
{
    extern __shared__ __half shh[];
    __half* Asm = shh;
    __half* Bsm = shh + 3 * A_STG;

    const int tid  = threadIdx.x;
    const int lane = tid & 31;
    const int warp = tid >> 5;
    const int wm = warp >> 2;
    const int wn = warp & 3;
    const int m_w = wm * 64;
    const int n_w = wn * 64;
    const int r4 = lane >> 2;
    const int c4 = lane & 3;
    const int bx = blockIdx.x, by = blockIdx.y;

    const __half* Ab = A  + (size_t)by * BM * K;
    const __half* Bb = Bt + (size_t)bx * BN * K;

    auto load_tile = [&](int buf, int k0) {
        __half* Ad = Asm + buf * A_STG;
        __half* Bd = Bsm + buf * B_STG;
#pragma unroll
        for (int i = 0; i < 2; i++) {
            int idx = tid + i * 256;
            int row = idx >> 2, kq = (idx & 3) * 8;
            cp_async16(Ad + row * HSTR + kq, Ab + (size_t)row * K + k0 + kq);
        }
#pragma unroll
        for (int i = 0; i < 4; i++) {
            int idx = tid + i * 256;
            int row = idx >> 2, kq = (idx & 3) * 8;
            cp_async16(Bd + row * HSTR + kq, Bb + (size_t)row * K + k0 + kq);
        }
        CP_COMMIT();
    };

    float acc[4][8][4] = {};

    const int nT = K / BKH;
    load_tile(0, 0);
    load_tile(1, BKH);

#pragma unroll 1
    for (int t = 0; t < nT; t++) {
        if (t + 1 < nT) { CP_WAIT1(); } else { CP_WAIT0(); }
        __syncthreads();
        if (t + 2 < nT) load_tile((t + 2) % 3, (t + 2) * BKH);

        const __half* Ac = Asm + (t % 3) * A_STG;
        const __half* Bc = Bsm + (t % 3) * B_STG;
#pragma unroll
        for (int ks = 0; ks < 2; ks++) {
            const int kc = ks * 16;
            uint32_t a[4][4], b[8][2];
#pragma unroll
            for (int mi = 0; mi < 4; mi++) {
                int m0 = m_w + mi * 16;
                a[mi][0] = *reinterpret_cast<const uint32_t*>(Ac + (m0 + r4) * HSTR + kc + 2 * c4);
                a[mi][1] = *reinterpret_cast<const uint32_t*>(Ac + (m0 + r4 + 8) * HSTR + kc + 2 * c4);
                a[mi][2] = *reinterpret_cast<const uint32_t*>(Ac + (m0 + r4) * HSTR + kc + 2 * c4 + 8);
                a[mi][3] = *reinterpret_cast<const uint32_t*>(Ac + (m0 + r4 + 8) * HSTR + kc + 2 * c4 + 8);
            }
#pragma unroll
            for (int ni = 0; ni < 8; ni++) {
                int n0 = n_w + ni * 8;
                b[ni][0] = *reinterpret_cast<const uint32_t*>(Bc + (n0 + r4) * HSTR + kc + 2 * c4);
                b[ni][1] = *reinterpret_cast<const uint32_t*>(Bc + (n0 + r4) * HSTR + kc + 2 * c4 + 8);
            }
#pragma unroll
            for (int mi = 0; mi < 4; mi++)
#pragma unroll
                for (int ni = 0; ni < 8; ni++)
                    mma_f16(acc[mi][ni], a[mi], b[ni]);
        }
    }

    const int row_base = by * BM + m_w;
    const int col_base = bx * BN + n_w;
#pragma unroll
    for (int mi = 0; mi < 4; mi++) {
#pragma unroll
        for (int ni = 0; ni < 8; ni++) {
            int c0 = col_base + ni * 8 + 2 * c4;
            float2 bb = *reinterpret_cast<const float2*>(bias + c0);
#pragma unroll
            for (int half = 0; half < 2; half++) {
                int r0 = row_base + mi * 16 + r4 + half * 8;
                float v0 = acc[mi][ni][half * 2]     + bb.x;
                float v1 = acc[mi][ni][half * 2 + 1] + bb.y;
                if (RELU) { v0 = fmaxf(v0, 0.f); v1 = fmaxf(v1, 0.f); }
                if (RES) {
                    float2 rr = *reinterpret_cast<const float2*>(resid + (size_t)r0 * N + c0);
                    v0 += rr.x; v1 += rr.y;
                }
                if (HALFOUT) {
                    *reinterpret_cast<__half2*>((__half*)Cout + (size_t)r0 * N + c0) =
                        __floats2half2_rn(v0, v1);
                } else {
                    float2 o2 = {v0, v1};
                    *reinterpret_cast<float2*>((float*)Cout + (size_t)r0 * N + c0) = o2;
                }
            }
        }
    }
}

// ---------------- launch ----------------
extern "C" void kernel_launch(void* const* d_in, const int* in_sizes, int n_in,
                              void* d_out, int out_size)
{
    (void)in_sizes; (void)n_in; (void)out_size;
    const float* x   = (const float*)d_in[0];
    const float* Wq  = (const float*)d_in[1];
    const float* Wk  = (const float*)d_in[2];
    const float* Wv  = (const float*)d_in[3];
    const float* Wo  = (const float*)d_in[4];
    const float* bo  = (const float*)d_in[5];
    const float* W1  = (const float*)d_in[6];
    const float* b1  = (const float*)d_in[7];
    const float* W2  = (const float*)d_in[8];
    const float* b2  = (const float*)d_in[9];
    const float* g1  = (const float*)d_in[10];
    const float* be1 = (const float*)d_in[11];
    const float* g2  = (const float*)d_in[12];
    const float* be2 = (const float*)d_in[13];
    float* out = (float*)d_out;

    float *x1;
    __half *nxh, *qb, *kb, *vb, *ob, *nx2, *h1, *woT, *w1T, *w2T, *wqT, *wkT, *wvT;
    cudaGetSymbolAddress((void**)&nxh, g_nxh);
    cudaGetSymbolAddress((void**)&qb,  g_q);
    cudaGetSymbolAddress((void**)&kb,  g_k);
    cudaGetSymbolAddress((void**)&vb,  g_v);
    cudaGetSymbolAddress((void**)&ob,  g_o);
    cudaGetSymbolAddress((void**)&x1,  g_x1);
    cudaGetSymbolAddress((void**)&nx2, g_nx2);
    cudaGetSymbolAddress((void**)&h1,  g_h1);
    cudaGetSymbolAddress((void**)&woT, g_woT);
    cudaGetSymbolAddress((void**)&w1T, g_w1T);
    cudaGetSymbolAddress((void**)&w2T, g_w2T);
    cudaGetSymbolAddress((void**)&wqT, g_wqT);
    cudaGetSymbolAddress((void**)&wkT, g_wkT);
    cudaGetSymbolAddress((void**)&wvT, g_wvT);

    cudaFuncSetAttribute(hgemm_kernel<0, 1, 0>, cudaFuncAttributeMaxDynamicSharedMemorySize,
                         GEMM_SMEM_BYTES);
    cudaFuncSetAttribute(hgemm_kernel<1, 0, 1>, cudaFuncAttributeMaxDynamicSharedMemorySize,
                         GEMM_SMEM_BYTES);

    // fork a side stream (capture-legal): big weight transposes run concurrently
    // with the LN1 -> QKV -> attention chain; join before the Wo GEMM.
    cudaStream_t s2 = 0;
    cudaEvent_t evFork = 0, evJoin = 0;
    bool forked = false;
    if (cudaStreamCreateWithFlags(&s2, cudaStreamNonBlocking) == cudaSuccess &&
        cudaEventCreateWithFlags(&evFork, cudaEventDisableTiming) == cudaSuccess &&
        cudaEventCreateWithFlags(&evJoin, cudaEventDisableTiming) == cudaSuccess) {
        forked = (cudaEventRecord(evFork, 0) == cudaSuccess) &&
                 (cudaStreamWaitEvent(s2, evFork, 0) == cudaSuccess);
    }
    cudaStream_t ts = forked ? s2 : 0;

    // 0a) big weight transposes (side stream if forked)
    transpose_h_kernel<<<dim3(E_ / 32, E_ / 32), dim3(32, 8), 0, ts>>>(Wo, woT, E_, E_);
    transpose_h_kernel<<<dim3(F_ / 32, E_ / 32), dim3(32, 8), 0, ts>>>(W1, w1T, E_, F_);
    transpose_h_kernel<<<dim3(E_ / 32, F_ / 32), dim3(32, 8), 0, ts>>>(W2, w2T, F_, E_);
    if (forked) {
        cudaEventRecord(evJoin, s2);
    }

    // 0b) tiny per-head weight transposes (main stream; QKV depends on them)
    transpose_h_kernel<<<dim3(2, 2), dim3(32, 8)>>>(Wq, wqT, D_, D_);
    transpose_h_kernel<<<dim3(2, 2), dim3(32, 8)>>>(Wk, wkT, D_, D_);
    transpose_h_kernel<<<dim3(2, 2), dim3(32, 8)>>>(Wv, wvT, D_, D_);
    // 1) LN1 (fp16 out)
    ln_kernel<1><<<TOK, 256>>>(x, g1, be1, nxh);
    // 2) QKV projections (fp16 mma)
    qkv_kernel<<<dim3(S_ / 64, H_, B_), 128>>>(nxh, wqT, wkT, wvT, qb, kb, vb);
    // 3) causal flash attention (register softmax) -> o fp16
    attn_kernel<<<dim3(S_ / 64, H_, B_), 128>>>(qb, kb, vb, ob);

    // join: Wo/W1/W2 transposes must be done before the GEMMs
    if (forked) {
        cudaStreamWaitEvent(0, evJoin, 0);
    }

    // 4) x1 = x + o @ Wo + bo   (f32 out)
    hgemm_kernel<0, 1, 0><<<dim3(E_ / BN, TOK / BM), 256, GEMM_SMEM_BYTES>>>(ob, woT, bo, x, x1, TOK, E_, E_);
    // 5) LN2 (fp16 out)
    ln_kernel<1><<<TOK, 256>>>(x1, g2, be2, nx2);
    // 6) h1 = relu(nx2 @ W1 + b1)  (fp16 out)
    hgemm_kernel<1, 0, 1><<<dim3(F_ / BN, TOK / BM), 256, GEMM_SMEM_BYTES>>>(nx2, w1T, b1, nullptr, h1, TOK, F_, E_);
    // 7) out = x1 + h1 @ W2 + b2   (f32 out)
    hgemm_kernel<0, 1, 0><<<dim3(E_ / BN, TOK / BM), 256, GEMM_SMEM_BYTES>>>(h1, w2T, b2, x1, out, TOK, E_, F_);
    // note: s2/evFork/evJoin intentionally not destroyed — handles are tiny,
    // kernel_launch is called only a few times, and destroying mid-capture is risky.
}

// round 12
// speedup vs baseline: 1.9457x; 1.0778x over previous
#include <cuda_runtime.h>
#include <cuda_fp16.h>
#include <math.h>
#include <stdint.h>

#define B_ 8
#define S_ 1024
#define E_ 1024
#define H_ 16
#define D_ 64
#define F_ 4096
#define TOK (B_ * S_)  // 8192

// ---------------- scratch (static device globals; no allocation) ----------------
__device__ __half g_nxh[(size_t)TOK * E_];
__device__ __half g_q  [(size_t)TOK * E_];
__device__ __half g_k  [(size_t)TOK * E_];
__device__ __half g_v  [(size_t)TOK * E_];
__device__ __half g_o  [(size_t)TOK * E_];
__device__ float  g_x1 [(size_t)TOK * E_];
__device__ __half g_nx2[(size_t)TOK * E_];
__device__ __half g_h1 [(size_t)TOK * F_];
__device__ __half g_woT[(size_t)E_ * E_];
__device__ __half g_w1T[(size_t)F_ * E_];
__device__ __half g_w2T[(size_t)E_ * F_];
__device__ __half g_wqT[(size_t)D_ * D_];
__device__ __half g_wkT[(size_t)D_ * D_];
__device__ __half g_wvT[(size_t)D_ * D_];

// ---------------- helpers ----------------
__device__ __forceinline__ void cp_async16(void* smem, const void* gmem) {
    uint32_t s = (uint32_t)__cvta_generic_to_shared(smem);
    asm volatile("cp.async.cg.shared.global [%0], [%1], 16;\n" :: "r"(s), "l"(gmem));
}
#define CP_COMMIT() asm volatile("cp.async.commit_group;\n" ::: "memory")
#define CP_WAIT0()  asm volatile("cp.async.wait_group 0;\n" ::: "memory")
#define CP_WAIT1()  asm volatile("cp.async.wait_group 1;\n" ::: "memory")

__device__ __forceinline__ void mma_f16(float c[4], const uint32_t a[4], const uint32_t b[2]) {
    asm volatile(
        "mma.sync.aligned.m16n8k16.row.col.f32.f16.f16.f32 "
        "{%0,%1,%2,%3}, {%4,%5,%6,%7}, {%8,%9}, {%0,%1,%2,%3};\n"
        : "+f"(c[0]), "+f"(c[1]), "+f"(c[2]), "+f"(c[3])
        : "r"(a[0]), "r"(a[1]), "r"(a[2]), "r"(a[3]), "r"(b[0]), "r"(b[1]));
}
__device__ __forceinline__ uint32_t packh2(float a, float b) {
    __half2 h = __floats2half2_rn(a, b);
    return *reinterpret_cast<uint32_t*>(&h);
}
__device__ __forceinline__ void ldsm_x4_trans(uint32_t r[4], uint32_t saddr) {
    asm volatile("ldmatrix.sync.aligned.m8n8.x4.trans.shared.b16 {%0,%1,%2,%3}, [%4];"
                 : "=r"(r[0]), "=r"(r[1]), "=r"(r[2]), "=r"(r[3]) : "r"(saddr));
}

// ---------------- weight transpose + fp16 round: in [K][N] f32 -> out [N][K] f16 ----------
__global__ __launch_bounds__(256) void transpose_h_kernel(const float* __restrict__ in,
                                                          __half* __restrict__ out,
                                                          int K, int N)
{
    __shared__ float tile[32][33];
    int bx = blockIdx.x;
    int by = blockIdx.y;
    int x = bx * 32 + threadIdx.x;
    int y0 = by * 32 + threadIdx.y;
#pragma unroll
    for (int j = 0; j < 32; j += 8)
        tile[threadIdx.y + j][threadIdx.x] = in[(size_t)(y0 + j) * N + x];
    __syncthreads();
    int xo = by * 32 + threadIdx.x;
    int yo = bx * 32 + threadIdx.y;
#pragma unroll
    for (int j = 0; j < 32; j += 8)
        out[(size_t)(yo + j) * K + xo] = __float2half_rn(tile[threadIdx.x][threadIdx.y + j]);
}

// ---------------- LayerNorm: one block per row of 1024 ----------------
template <int HALFOUT>
__global__ __launch_bounds__(256) void ln_kernel(const float* __restrict__ x,
                                                 const float* __restrict__ g,
                                                 const float* __restrict__ be,
                                                 void* __restrict__ out)
{
    int row = blockIdx.x;
    int tid = threadIdx.x;
    const float4* xr = reinterpret_cast<const float4*>(x + (size_t)row * E_);
    float4 a = xr[tid];
    float s  = a.x + a.y + a.z + a.w;
    float ss = a.x * a.x + a.y * a.y + a.z * a.z + a.w * a.w;
#pragma unroll
    for (int o = 16; o > 0; o >>= 1) {
        s  += __shfl_xor_sync(0xffffffffu, s,  o);
        ss += __shfl_xor_sync(0xffffffffu, ss, o);
    }
    __shared__ float sm[8], sm2[8];
    int w = tid >> 5, lane = tid & 31;
    if (lane == 0) { sm[w] = s; sm2[w] = ss; }
    __syncthreads();
    if (tid < 32) {
        s  = (tid < 8) ? sm[tid]  : 0.f;
        ss = (tid < 8) ? sm2[tid] : 0.f;
#pragma unroll
        for (int o = 4; o > 0; o >>= 1) {
            s  += __shfl_xor_sync(0xffffffffu, s,  o);
            ss += __shfl_xor_sync(0xffffffffu, ss, o);
        }
        if (tid == 0) { sm[0] = s; sm2[0] = ss; }
    }
    __syncthreads();
    float mean = sm[0] * (1.0f / E_);
    float var  = sm2[0] * (1.0f / E_) - mean * mean;
    float inv  = rsqrtf(var + 1e-5f);
    float4 gg = reinterpret_cast<const float4*>(g)[tid];
    float4 bb = reinterpret_cast<const float4*>(be)[tid];
    float4 o4;
    o4.x = (a.x - mean) * inv * gg.x + bb.x;
    o4.y = (a.y - mean) * inv * gg.y + bb.y;
    o4.z = (a.z - mean) * inv * gg.z + bb.z;
    o4.w = (a.w - mean) * inv * gg.w + bb.w;
    if (HALFOUT) {
        __half2* op = reinterpret_cast<__half2*>((__half*)out + (size_t)row * E_ + tid * 4);
        op[0] = __floats2half2_rn(o4.x, o4.y);
        op[1] = __floats2half2_rn(o4.z, o4.w);
    } else {
        reinterpret_cast<float4*>((float*)out + (size_t)row * E_)[tid] = o4;
    }
}

// ---------------- QKV projections via fp16 mma: per (64-token tile, head, batch) --------
#define AST 72   // halves; conflict-free for fragment pattern

__global__ __launch_bounds__(128) void qkv_kernel(const __half* __restrict__ nxh,
                                                  const __half* __restrict__ wqT,
                                                  const __half* __restrict__ wkT,
                                                  const __half* __restrict__ wvT,
                                                  __half* __restrict__ q,
                                                  __half* __restrict__ k,
                                                  __half* __restrict__ v)
{
    __shared__ __half Xh[64 * AST];
    __shared__ __half Wh[64 * AST];
    int st = blockIdx.x, h = blockIdx.y, b = blockIdx.z;
    int tid  = threadIdx.x;
    int lane = tid & 31, warp = tid >> 5;
    int m0 = warp * 16;
    int r4 = lane >> 2, c4 = lane & 3;

#pragma unroll
    for (int it = 0; it < 4; it++) {
        int idx = tid + it * 128;
        int r = idx >> 3, c8 = (idx & 7) * 8;
        uint4 raw = *reinterpret_cast<const uint4*>(
            nxh + ((size_t)(b * S_ + st * 64 + r)) * E_ + h * 64 + c8);
        *reinterpret_cast<uint4*>(Xh + r * AST + c8) = raw;
    }

    const __half* Wm[3] = {wqT, wkT, wvT};
    __half*       Om[3] = {q, k, v};
    size_t obase = ((size_t)(b * H_ + h) * S_ + st * 64) * D_;

#pragma unroll 1
    for (int m = 0; m < 3; m++) {
        __syncthreads();
#pragma unroll
        for (int it = 0; it < 4; it++) {
            int idx = tid + it * 128;
            int r = idx >> 3, c8 = (idx & 7) * 8;
            uint4 raw = *reinterpret_cast<const uint4*>(Wm[m] + r * 64 + c8);
            *reinterpret_cast<uint4*>(Wh + r * AST + c8) = raw;
        }
        __syncthreads();

        float acc[8][4] = {};
#pragma unroll
        for (int ks = 0; ks < 4; ks++) {
            int kc = ks * 16;
            uint32_t a[4];
            a[0] = *reinterpret_cast<const uint32_t*>(Xh + (m0 + r4) * AST + kc + 2 * c4);
            a[1] = *reinterpret_cast<const uint32_t*>(Xh + (m0 + r4 + 8) * AST + kc + 2 * c4);
            a[2] = *reinterpret_cast<const uint32_t*>(Xh + (m0 + r4) * AST + kc + 2 * c4 + 8);
            a[3] = *reinterpret_cast<const uint32_t*>(Xh + (m0 + r4 + 8) * AST + kc + 2 * c4 + 8);
#pragma unroll
            for (int ni = 0; ni < 8; ni++) {
                int n0 = ni * 8;
                uint32_t bf[2];
                bf[0] = *reinterpret_cast<const uint32_t*>(Wh + (n0 + r4) * AST + kc + 2 * c4);
                bf[1] = *reinterpret_cast<const uint32_t*>(Wh + (n0 + r4) * AST + kc + 2 * c4 + 8);
                mma_f16(acc[ni], a, bf);
            }
        }
        __half* dst = Om[m] + obase;
#pragma unroll
        for (int ni = 0; ni < 8; ni++) {
            int cc = ni * 8 + 2 * c4;
            *reinterpret_cast<uint32_t*>(dst + (m0 + r4) * D_ + cc)     = packh2(acc[ni][0], acc[ni][1]);
            *reinterpret_cast<uint32_t*>(dst + (m0 + r4 + 8) * D_ + cc) = packh2(acc[ni][2], acc[ni][3]);
        }
    }
}

// ---------------- Causal flash attention: register softmax, ldmatrix.trans V,
//                  cp.async double-buffered K/V, heaviest-first scheduling ------------
__global__ __launch_bounds__(128) void attn_kernel(const __half* __restrict__ q,
                                                   const __half* __restrict__ k,
                                                   const __half* __restrict__ v,
                                                   __half* __restrict__ o)
{
    __shared__ __half Qh[64 * AST];
    __shared__ __half Kh[2][64 * AST];
    __shared__ __half Vh[2][64 * AST];   // row-major [s][d]

    // heaviest-first: high qt blocks launch first
    int qt = (int)gridDim.x - 1 - (int)blockIdx.x;
    int h = blockIdx.y, b = blockIdx.z;
    int tid  = threadIdx.x;
    int lane = tid & 31, warp = tid >> 5;
    int m0 = warp * 16;
    int r4 = lane >> 2, c4 = lane & 3;
    size_t head_base = (size_t)(b * H_ + h) * S_ * D_;
    const __half2 hscale = __float2half2_rn(0.03125f);  // 1/32 exact

    // ldmatrix.trans per-lane address offsets (within a V tile)
    const int lm = lane >> 3;            // matrix id 0..3
    const int lj = lane & 7;             // row within matrix
    const int lrow_off = (lm & 1) * 8 + lj;   // + kc
    const int lcol_off = (lm >> 1) * 8;       // + g*16

    // load Q (scaled)
#pragma unroll
    for (int it = 0; it < 4; it++) {
        int idx = tid + it * 128;
        int r = idx >> 3, c8 = (idx & 7) * 8;
        uint4 raw = *reinterpret_cast<const uint4*>(q + head_base + (size_t)(qt * 64 + r) * 64 + c8);
        __half2* hp = reinterpret_cast<__half2*>(&raw);
#pragma unroll
        for (int j = 0; j < 4; j++) hp[j] = __hmul2(hp[j], hscale);
        *reinterpret_cast<uint4*>(Qh + r * AST + c8) = raw;
    }

    auto stage = [&](int buf, int kt) {
#pragma unroll
        for (int it = 0; it < 4; it++) {
            int idx = tid + it * 128;
            int r = idx >> 3, c8 = (idx & 7) * 8;
            cp_async16(&Kh[buf][r * AST + c8], k + head_base + (size_t)(kt * 64 + r) * 64 + c8);
            cp_async16(&Vh[buf][r * AST + c8], v + head_base + (size_t)(kt * 64 + r) * 64 + c8);
        }
        CP_COMMIT();
    };

    float m_0 = -1e30f, m_1 = -1e30f, l_0 = 0.f, l_1 = 0.f;
    float acc_o[8][4] = {};

    stage(0, 0);

    for (int kt = 0; kt <= qt; kt++) {
        int buf = kt & 1;
        CP_WAIT0();
        __syncthreads();   // buf filled for all warps; all warps done reading buf^1 (iter kt-1)
        if (kt + 1 <= qt) stage(buf ^ 1, kt + 1);

        // ---- S = Q @ K^T : warp computes 16x64 in registers ----
        float s[8][4] = {};
#pragma unroll
        for (int ks = 0; ks < 4; ks++) {
            int kc = ks * 16;
            uint32_t a[4];
            a[0] = *reinterpret_cast<const uint32_t*>(Qh + (m0 + r4) * AST + kc + 2 * c4);
            a[1] = *reinterpret_cast<const uint32_t*>(Qh + (m0 + r4 + 8) * AST + kc + 2 * c4);
            a[2] = *reinterpret_cast<const uint32_t*>(Qh + (m0 + r4) * AST + kc + 2 * c4 + 8);
            a[3] = *reinterpret_cast<const uint32_t*>(Qh + (m0 + r4 + 8) * AST + kc + 2 * c4 + 8);
#pragma unroll
            for (int ni = 0; ni < 8; ni++) {
                int n0 = ni * 8;
                uint32_t bf[2];
                bf[0] = *reinterpret_cast<const uint32_t*>(&Kh[buf][(n0 + r4) * AST + kc + 2 * c4]);
                bf[1] = *reinterpret_cast<const uint32_t*>(&Kh[buf][(n0 + r4) * AST + kc + 2 * c4 + 8]);
                mma_f16(s[ni], a, bf);
            }
        }

        if (kt == qt) {
            int row0 = m0 + r4, row1 = m0 + r4 + 8;
#pragma unroll
            for (int ni = 0; ni < 8; ni++) {
                int col = ni * 8 + 2 * c4;
                if (col > row0)     s[ni][0] = -1e30f;
                if (col + 1 > row0) s[ni][1] = -1e30f;
                if (col > row1)     s[ni][2] = -1e30f;
                if (col + 1 > row1) s[ni][3] = -1e30f;
            }
        }

        // ---- register softmax ----
        float mx0 = -1e30f, mx1 = -1e30f;
#pragma unroll
        for (int ni = 0; ni < 8; ni++) {
            mx0 = fmaxf(mx0, fmaxf(s[ni][0], s[ni][1]));
            mx1 = fmaxf(mx1, fmaxf(s[ni][2], s[ni][3]));
        }
        mx0 = fmaxf(mx0, __shfl_xor_sync(0xffffffffu, mx0, 1));
        mx0 = fmaxf(mx0, __shfl_xor_sync(0xffffffffu, mx0, 2));
        mx1 = fmaxf(mx1, __shfl_xor_sync(0xffffffffu, mx1, 1));
        mx1 = fmaxf(mx1, __shfl_xor_sync(0xffffffffu, mx1, 2));

        float mn0 = fmaxf(m_0, mx0), mn1 = fmaxf(m_1, mx1);
        float corr0 = expf(m_0 - mn0), corr1 = expf(m_1 - mn1);
        float rs0 = 0.f, rs1 = 0.f;
#pragma unroll
        for (int ni = 0; ni < 8; ni++) {
            s[ni][0] = expf(s[ni][0] - mn0);
            s[ni][1] = expf(s[ni][1] - mn0);
            s[ni][2] = expf(s[ni][2] - mn1);
            s[ni][3] = expf(s[ni][3] - mn1);
            rs0 += s[ni][0] + s[ni][1];
            rs1 += s[ni][2] + s[ni][3];
        }
        rs0 += __shfl_xor_sync(0xffffffffu, rs0, 1);
        rs0 += __shfl_xor_sync(0xffffffffu, rs0, 2);
        rs1 += __shfl_xor_sync(0xffffffffu, rs1, 1);
        rs1 += __shfl_xor_sync(0xffffffffu, rs1, 2);
        l_0 = l_0 * corr0 + rs0;  m_0 = mn0;
        l_1 = l_1 * corr1 + rs1;  m_1 = mn1;

        // pack P into A-fragments (S C-frag layout == P A-frag layout)
        uint32_t pa[4][4];
#pragma unroll
        for (int kk = 0; kk < 4; kk++) {
            pa[kk][0] = packh2(s[2 * kk][0],     s[2 * kk][1]);
            pa[kk][1] = packh2(s[2 * kk][2],     s[2 * kk][3]);
            pa[kk][2] = packh2(s[2 * kk + 1][0], s[2 * kk + 1][1]);
            pa[kk][3] = packh2(s[2 * kk + 1][2], s[2 * kk + 1][3]);
        }

        // ---- O = O*corr + P @ V  (V B-fragments via ldmatrix.trans) ----
#pragma unroll
        for (int ni = 0; ni < 8; ni++) {
            acc_o[ni][0] *= corr0; acc_o[ni][1] *= corr0;
            acc_o[ni][2] *= corr1; acc_o[ni][3] *= corr1;
        }
        uint32_t vbase = (uint32_t)__cvta_generic_to_shared(&Vh[buf][0]);
#pragma unroll
        for (int kk = 0; kk < 4; kk++) {
            int kc = kk * 16;
#pragma unroll
            for (int g = 0; g < 4; g++) {
                uint32_t r[4];
                uint32_t addr = vbase + (uint32_t)(((kc + lrow_off) * AST + g * 16 + lcol_off) * 2);
                ldsm_x4_trans(r, addr);
                uint32_t b0[2] = {r[0], r[1]};
                uint32_t b1[2] = {r[2], r[3]};
                mma_f16(acc_o[2 * g],     pa[kk], b0);
                mma_f16(acc_o[2 * g + 1], pa[kk], b1);
            }
        }
    }

    // epilogue: normalize, fp16, token-major [B,S,H,D]
    float inv0 = 1.0f / l_0;
    float inv1 = 1.0f / l_1;
    __half* ob = o + ((size_t)(b * S_ + qt * 64)) * E_ + h * 64;
#pragma unroll
    for (int ni = 0; ni < 8; ni++) {
        int cc = ni * 8 + 2 * c4;
        *reinterpret_cast<uint32_t*>(ob + (size_t)(m0 + r4) * E_ + cc) =
            packh2(acc_o[ni][0] * inv0, acc_o[ni][1] * inv0);
        *reinterpret_cast<uint32_t*>(ob + (size_t)(m0 + r4 + 8) * E_ + cc) =
            packh2(acc_o[ni][2] * inv1, acc_o[ni][3] * inv1);
    }
}

// ---------------- FP16 GEMM: 128x256x32 tiles, warp 64x64, 3-stage cp.async ------------
#define BM 128
#define BN 256
#define BKH 32
#define HSTR 40
#define A_STG (BM * HSTR)
#define B_STG (BN * HSTR)
#define GEMM_SMEM_BYTES (3 * (A_STG + B_STG) * 2)   // 92160

template <int RELU, int RES, int HALFOUT>
__global__ __launch_bounds__(256) void hgemm_kernel(const __half* __restrict__ A,
                                                    const __half* __restrict__ Bt,
                                                    const float* __restrict__ bias,
                                                    const float* __restrict__ resid,
                                                    void* __restrict__ Cout,
                                                    int M, int N, int K)
{
    extern __shared__ __half shh[];
    __half* Asm = shh;
    __half* Bsm = shh + 3 * A_STG;

    const int tid  = threadIdx.x;
    const int lane = tid & 31;
    const int warp = tid >> 5;
    const int wm = warp >> 2;
    const int wn = warp & 3;
    const int m_w = wm * 64;
    const int n_w = wn * 64;
    const int r4 = lane >> 2;
    const int c4 = lane & 3;
    const int bx = blockIdx.x, by = blockIdx.y;

    const __half* Ab = A  + (size_t)by * BM * K;
    const __half* Bb = Bt + (size_t)bx * BN * K;

    auto load_tile = [&](int buf, int k0) {
        __half* Ad = Asm + buf * A_STG;
        __half* Bd = Bsm + buf * B_STG;
#pragma unroll
        for (int i = 0; i < 2; i++) {
            int idx = tid + i * 256;
            int row = idx >> 2, kq = (idx & 3) * 8;
            cp_async16(Ad + row * HSTR + kq, Ab + (size_t)row * K + k0 + kq);
        }
#pragma unroll
        for (int i = 0; i < 4; i++) {
            int idx = tid + i * 256;
            int row = idx >> 2, kq = (idx & 3) * 8;
            cp_async16(Bd + row * HSTR + kq, Bb + (size_t)row * K + k0 + kq);
        }
        CP_COMMIT();
    };

    float acc[4][8][4] = {};

    const int nT = K / BKH;
    load_tile(0, 0);
    load_tile(1, BKH);

#pragma unroll 1
    for (int t = 0; t < nT; t++) {
        if (t + 1 < nT) { CP_WAIT1(); } else { CP_WAIT0(); }
        __syncthreads();
        if (t + 2 < nT) load_tile((t + 2) % 3, (t + 2) * BKH);

        const __half* Ac = Asm + (t % 3) * A_STG;
        const __half* Bc = Bsm + (t % 3) * B_STG;
#pragma unroll
        for (int ks = 0; ks < 2; ks++) {
            const int kc = ks * 16;
            uint32_t a[4][4], b[8][2];
#pragma unroll
            for (int mi = 0; mi < 4; mi++) {
                int m0 = m_w + mi * 16;
                a[mi][0] = *reinterpret_cast<const uint32_t*>(Ac + (m0 + r4) * HSTR + kc + 2 * c4);
                a[mi][1] = *reinterpret_cast<const uint32_t*>(Ac + (m0 + r4 + 8) * HSTR + kc + 2 * c4);
                a[mi][2] = *reinterpret_cast<const uint32_t*>(Ac + (m0 + r4) * HSTR + kc + 2 * c4 + 8);
                a[mi][3] = *reinterpret_cast<const uint32_t*>(Ac + (m0 + r4 + 8) * HSTR + kc + 2 * c4 + 8);
            }
#pragma unroll
            for (int ni = 0; ni < 8; ni++) {
                int n0 = n_w + ni * 8;
                b[ni][0] = *reinterpret_cast<const uint32_t*>(Bc + (n0 + r4) * HSTR + kc + 2 * c4);
                b[ni][1] = *reinterpret_cast<const uint32_t*>(Bc + (n0 + r4) * HSTR + kc + 2 * c4 + 8);
            }
#pragma unroll
            for (int mi = 0; mi < 4; mi++)
#pragma unroll
                for (int ni = 0; ni < 8; ni++)
                    mma_f16(acc[mi][ni], a[mi], b[ni]);
        }
    }

    const int row_base = by * BM + m_w;
    const int col_base = bx * BN + n_w;
#pragma unroll
    for (int mi = 0; mi < 4; mi++) {
#pragma unroll
        for (int ni = 0; ni < 8; ni++) {
            int c0 = col_base + ni * 8 + 2 * c4;
            float2 bb = *reinterpret_cast<const float2*>(bias + c0);
#pragma unroll
            for (int half = 0; half < 2; half++) {
                int r0 = row_base + mi * 16 + r4 + half * 8;
                float v0 = acc[mi][ni][half * 2]     + bb.x;
                float v1 = acc[mi][ni][half * 2 + 1] + bb.y;
                if (RELU) { v0 = fmaxf(v0, 0.f); v1 = fmaxf(v1, 0.f); }
                if (RES) {
                    float2 rr = *reinterpret_cast<const float2*>(resid + (size_t)r0 * N + c0);
                    v0 += rr.x; v1 += rr.y;
                }
                if (HALFOUT) {
                    *reinterpret_cast<__half2*>((__half*)Cout + (size_t)r0 * N + c0) =
                        __floats2half2_rn(v0, v1);
                } else {
                    float2 o2 = {v0, v1};
                    *reinterpret_cast<float2*>((float*)Cout + (size_t)r0 * N + c0) = o2;
                }
            }
        }
    }
}

// ---------------- launch ----------------
extern "C" void kernel_launch(void* const* d_in, const int* in_sizes, int n_in,
                              void* d_out, int out_size)
{
    (void)in_sizes; (void)n_in; (void)out_size;
    const float* x   = (const float*)d_in[0];
    const float* Wq  = (const float*)d_in[1];
    const float* Wk  = (const float*)d_in[2];
    const float* Wv  = (const float*)d_in[3];
    const float* Wo  = (const float*)d_in[4];
    const float* bo  = (const float*)d_in[5];
    const float* W1  = (const float*)d_in[6];
    const float* b1  = (const float*)d_in[7];
    const float* W2  = (const float*)d_in[8];
    const float* b2  = (const float*)d_in[9];
    const float* g1  = (const float*)d_in[10];
    const float* be1 = (const float*)d_in[11];
    const float* g2  = (const float*)d_in[12];
    const float* be2 = (const float*)d_in[13];
    float* out = (float*)d_out;

    float *x1;
    __half *nxh, *qb, *kb, *vb, *ob, *nx2, *h1, *woT, *w1T, *w2T, *wqT, *wkT, *wvT;
    cudaGetSymbolAddress((void**)&nxh, g_nxh);
    cudaGetSymbolAddress((void**)&qb,  g_q);
    cudaGetSymbolAddress((void**)&kb,  g_k);
    cudaGetSymbolAddress((void**)&vb,  g_v);
    cudaGetSymbolAddress((void**)&ob,  g_o);
    cudaGetSymbolAddress((void**)&x1,  g_x1);
    cudaGetSymbolAddress((void**)&nx2, g_nx2);
    cudaGetSymbolAddress((void**)&h1,  g_h1);
    cudaGetSymbolAddress((void**)&woT, g_woT);
    cudaGetSymbolAddress((void**)&w1T, g_w1T);
    cudaGetSymbolAddress((void**)&w2T, g_w2T);
    cudaGetSymbolAddress((void**)&wqT, g_wqT);
    cudaGetSymbolAddress((void**)&wkT, g_wkT);
    cudaGetSymbolAddress((void**)&wvT, g_wvT);

    cudaFuncSetAttribute(hgemm_kernel<0, 1, 0>, cudaFuncAttributeMaxDynamicSharedMemorySize,
                         GEMM_SMEM_BYTES);
    cudaFuncSetAttribute(hgemm_kernel<1, 0, 1>, cudaFuncAttributeMaxDynamicSharedMemorySize,
                         GEMM_SMEM_BYTES);

    // fork a side stream (capture-legal): big weight transposes run concurrently
    // with the LN1 -> QKV -> attention chain; join before the Wo GEMM.
    cudaStream_t s2 = 0;
    cudaEvent_t evFork = 0, evJoin = 0;
    bool forked = false;
    if (cudaStreamCreateWithFlags(&s2, cudaStreamNonBlocking) == cudaSuccess &&
        cudaEventCreateWithFlags(&evFork, cudaEventDisableTiming) == cudaSuccess &&
        cudaEventCreateWithFlags(&evJoin, cudaEventDisableTiming) == cudaSuccess) {
        forked = (cudaEventRecord(evFork, 0) == cudaSuccess) &&
                 (cudaStreamWaitEvent(s2, evFork, 0) == cudaSuccess);
    }
    cudaStream_t ts = forked ? s2 : 0;

    // 0a) big weight transposes (side stream if forked)
    transpose_h_kernel<<<dim3(E_ / 32, E_ / 32), dim3(32, 8), 0, ts>>>(Wo, woT, E_, E_);
    transpose_h_kernel<<<dim3(F_ / 32, E_ / 32), dim3(32, 8), 0, ts>>>(W1, w1T, E_, F_);
    transpose_h_kernel<<<dim3(E_ / 32, F_ / 32), dim3(32, 8), 0, ts>>>(W2, w2T, F_, E_);
    if (forked) {
        cudaEventRecord(evJoin, s2);
    }

    // 0b) tiny per-head weight transposes (main stream; QKV depends on them)
    transpose_h_kernel<<<dim3(2, 2), dim3(32, 8)>>>(Wq, wqT, D_, D_);
    transpose_h_kernel<<<dim3(2, 2), dim3(32, 8)>>>(Wk, wkT, D_, D_);
    transpose_h_kernel<<<dim3(2, 2), dim3(32, 8)>>>(Wv, wvT, D_, D_);
    // 1) LN1 (fp16 out)
    ln_kernel<1><<<TOK, 256>>>(x, g1, be1, nxh);
    // 2) QKV projections (fp16 mma)
    qkv_kernel<<<dim3(S_ / 64, H_, B_), 128>>>(nxh, wqT, wkT, wvT, qb, kb, vb);
    // 3) causal flash attention -> o fp16
    attn_kernel<<<dim3(S_ / 64, H_, B_), 128>>>(qb, kb, vb, ob);

    // join: Wo/W1/W2 transposes must be done before the GEMMs
    if (forked) {
        cudaStreamWaitEvent(0, evJoin, 0);
    }

    // 4) x1 = x + o @ Wo + bo   (f32 out)
    hgemm_kernel<0, 1, 0><<<dim3(E_ / BN, TOK / BM), 256, GEMM_SMEM_BYTES>>>(ob, woT, bo, x, x1, TOK, E_, E_);
    // 5) LN2 (fp16 out)
    ln_kernel<1><<<TOK, 256>>>(x1, g2, be2, nx2);
    // 6) h1 = relu(nx2 @ W1 + b1)  (fp16 out)
    hgemm_kernel<1, 0, 1><<<dim3(F_ / BN, TOK / BM), 256, GEMM_SMEM_BYTES>>>(nx2, w1T, b1, nullptr, h1, TOK, F_, E_);
    // 7) out = x1 + h1 @ W2 + b2   (f32 out)
    hgemm_kernel<0, 1, 0><<<dim3(E_ / BN, TOK / BM), 256, GEMM_SMEM_BYTES>>>(h1, w2T, b2, x1, out, TOK, E_, F_);
    // note: s2/evFork/evJoin intentionally not destroyed — handles are tiny,
    // kernel_launch is called only a few times, and destroying mid-capture is risky.
}